// round 7
// baseline (speedup 1.0000x reference)
#include <cuda_runtime.h>
#include <cuda_bf16.h>
#include <cstdint>

#define TT  4096     // T
#define DD  1024     // D
#define HH  16
#define DH  64
#define BHN 32       // B*H
#define ROWS 8192    // B*T
#define FD  512      // 2m
#define NSPLIT 16
#define MR2 (ROWS * HH)   // 131072 head-rows

// ---------------- scratch (device globals; no runtime allocation) ----------------
__device__ float g_Q[ROWS * DD];
__device__ float g_K[ROWS * DD];
__device__ float g_V[ROWS * DD];
__device__ float g_attn[ROWS * DD];
__device__ float g_Qf[BHN * TT * FD];
__device__ float g_Kf[BHN * TT * FD];
__device__ float g_KVpart[BHN * NSPLIT * FD * 65];
__device__ float g_KV[BHN * FD * 65];
__device__ float g_scale[MR2];
__device__ __nv_bfloat16 g_Ahi[ROWS * DD];
__device__ __nv_bfloat16 g_Alo[ROWS * DD];
__device__ __nv_bfloat16 g_Whi[DD * DD];
__device__ __nv_bfloat16 g_Wlo[DD * DD];

// =================== base-target PTX helpers (no tcgen05!) =======================
__device__ __forceinline__ uint32_t smem_u32(const void* p) {
    uint32_t a;
    asm("{ .reg .u64 t; cvta.to.shared.u64 t, %1; cvt.u32.u64 %0, t; }" : "=r"(a) : "l"(p));
    return a;
}
#define CP_ASYNC16(saddr, gptr) \
    asm volatile("cp.async.cg.shared.global [%0], [%1], 16;" :: "r"(saddr), "l"(gptr))
#define CP_ASYNC_COMMIT() asm volatile("cp.async.commit_group;" ::: "memory")
#define CP_ASYNC_WAIT1()  asm volatile("cp.async.wait_group 1;" ::: "memory")
#define CP_ASYNC_WAIT0()  asm volatile("cp.async.wait_group 0;" ::: "memory")
#define LDMATRIX_X4(r, addr) \
    asm volatile("ldmatrix.sync.aligned.m8n8.x4.shared.b16 {%0,%1,%2,%3}, [%4];" \
        : "=r"((r)[0]), "=r"((r)[1]), "=r"((r)[2]), "=r"((r)[3]) : "r"(addr))
#define LDMATRIX_X2(r, addr) \
    asm volatile("ldmatrix.sync.aligned.m8n8.x2.shared.b16 {%0,%1}, [%2];" \
        : "=r"((r)[0]), "=r"((r)[1]) : "r"(addr))
#define MMA16816(c, a, b) \
    asm volatile("mma.sync.aligned.m16n8k16.row.col.f32.bf16.bf16.f32 " \
        "{%0,%1,%2,%3}, {%4,%5,%6,%7}, {%8,%9}, {%0,%1,%2,%3};" \
        : "+f"((c)[0]), "+f"((c)[1]), "+f"((c)[2]), "+f"((c)[3]) \
        : "r"((a)[0]), "r"((a)[1]), "r"((a)[2]), "r"((a)[3]), "r"((b)[0]), "r"((b)[1]))
#define SWZ128(off) ((off) ^ (((off) >> 3) & 0x70))

// =================== HMMA bf16x3 split GEMM (big projections) ====================
// C[M,N] = A[M,K] * B[N,K]^T with A = Ahi+Alo, B = Bhi+Blo (bf16 splits of fp32).
// CTA tile 128x128, 8 warps (2M x 4N => 64x32/warp), K-chunk 32, 2-stage cp.async.
// Smem rows 64B (32 bf16); 16B chunks swizzled c' = c ^ ((row>>1)&3).
#define G_STAGE 32768
#define G_AHI 0
#define G_ALO 8192
#define G_BHI 16384
#define G_BLO 24576
#define G_TOTAL (2 * G_STAGE)

__global__ __launch_bounds__(256)
void gemm_tc(const __nv_bfloat16* __restrict__ Ahi, const __nv_bfloat16* __restrict__ Alo,
             const __nv_bfloat16* __restrict__ Bhi, const __nv_bfloat16* __restrict__ Blo,
             float* __restrict__ C, int M, int N, int K) {
    extern __shared__ char smem[];
    const uint32_t sbase = smem_u32(smem);
    const int tid = threadIdx.x;
    const int wid = tid >> 5, lane = tid & 31;
    const int warpM = (wid >> 2) * 64;
    const int warpN = (wid & 3) * 32;
    const int brow = blockIdx.y * 128;
    const int bcol = blockIdx.x * 128;

    float acc[4][4][4];
#pragma unroll
    for (int i = 0; i < 4; i++)
#pragma unroll
        for (int j = 0; j < 4; j++)
#pragma unroll
            for (int r = 0; r < 4; r++) acc[i][j][r] = 0.f;

    const int r0 = tid >> 2, c0 = tid & 3;
    const int r1 = (tid + 256) >> 2, c1 = c0;
    const uint32_t so0 = (uint32_t)(r0 * 64 + ((c0 ^ ((r0 >> 1) & 3)) * 16));
    const uint32_t so1 = (uint32_t)(r1 * 64 + ((c1 ^ ((r1 >> 1) & 3)) * 16));

    const int nchunk = K >> 5;

#define ISSUE_CHUNK(ch, stg) do { \
    const int _k0 = (ch) << 5; \
    const uint32_t _st = sbase + (stg) * G_STAGE; \
    const size_t _ga0 = (size_t)(brow + r0) * K + _k0 + c0 * 8; \
    const size_t _ga1 = (size_t)(brow + r1) * K + _k0 + c1 * 8; \
    const size_t _gb0 = (size_t)(bcol + r0) * K + _k0 + c0 * 8; \
    const size_t _gb1 = (size_t)(bcol + r1) * K + _k0 + c1 * 8; \
    CP_ASYNC16(_st + G_AHI + so0, Ahi + _ga0); \
    CP_ASYNC16(_st + G_AHI + so1, Ahi + _ga1); \
    CP_ASYNC16(_st + G_ALO + so0, Alo + _ga0); \
    CP_ASYNC16(_st + G_ALO + so1, Alo + _ga1); \
    CP_ASYNC16(_st + G_BHI + so0, Bhi + _gb0); \
    CP_ASYNC16(_st + G_BHI + so1, Bhi + _gb1); \
    CP_ASYNC16(_st + G_BLO + so0, Blo + _gb0); \
    CP_ASYNC16(_st + G_BLO + so1, Blo + _gb1); \
    CP_ASYNC_COMMIT(); \
} while (0)

    ISSUE_CHUNK(0, 0);

    for (int ch = 0; ch < nchunk; ch++) {
        const int s = ch & 1;
        if (ch + 1 < nchunk) { ISSUE_CHUNK(ch + 1, s ^ 1); CP_ASYNC_WAIT1(); }
        else                 { CP_ASYNC_WAIT0(); }
        __syncthreads();

        const uint32_t st = sbase + s * G_STAGE;
#pragma unroll
        for (int kk = 0; kk < 2; kk++) {
            const int cb = kk * 2;
            uint32_t bh[4][2], bl[4][2];
#pragma unroll
            for (int ni = 0; ni < 4; ni++) {
                const int n = warpN + ni * 8 + (lane & 7);
                const int chk = cb + ((lane >> 3) & 1);
                const uint32_t ad = st + G_BHI + (uint32_t)(n * 64 + ((chk ^ ((n >> 1) & 3)) * 16));
                LDMATRIX_X2(bh[ni], ad);
                LDMATRIX_X2(bl[ni], ad + 8192);
            }
            uint32_t af[4][4];
#pragma unroll
            for (int mi = 0; mi < 4; mi++) {
                const int m = warpM + mi * 16 + (lane & 15);
                const int chk = cb + (lane >> 4);
                const uint32_t ad = st + G_AHI + (uint32_t)(m * 64 + ((chk ^ ((m >> 1) & 3)) * 16));
                LDMATRIX_X4(af[mi], ad);
            }
#pragma unroll
            for (int mi = 0; mi < 4; mi++)
#pragma unroll
                for (int ni = 0; ni < 4; ni++) MMA16816(acc[mi][ni], af[mi], bh[ni]);
#pragma unroll
            for (int mi = 0; mi < 4; mi++)
#pragma unroll
                for (int ni = 0; ni < 4; ni++) MMA16816(acc[mi][ni], af[mi], bl[ni]);
#pragma unroll
            for (int mi = 0; mi < 4; mi++) {
                const int m = warpM + mi * 16 + (lane & 15);
                const int chk = cb + (lane >> 4);
                const uint32_t ad = st + G_ALO + (uint32_t)(m * 64 + ((chk ^ ((m >> 1) & 3)) * 16));
                LDMATRIX_X4(af[mi], ad);
            }
#pragma unroll
            for (int mi = 0; mi < 4; mi++)
#pragma unroll
                for (int ni = 0; ni < 4; ni++) MMA16816(acc[mi][ni], af[mi], bh[ni]);
        }
        __syncthreads();
    }
#undef ISSUE_CHUNK

#pragma unroll
    for (int mi = 0; mi < 4; mi++) {
        const int row = brow + warpM + mi * 16 + (lane >> 2);
#pragma unroll
        for (int ni = 0; ni < 4; ni++) {
            const int col = bcol + warpN + ni * 8 + (lane & 3) * 2;
            *(float2*)(C + (size_t)row * N + col)       = make_float2(acc[mi][ni][0], acc[mi][ni][1]);
            *(float2*)(C + (size_t)(row + 8) * N + col) = make_float2(acc[mi][ni][2], acc[mi][ni][3]);
        }
    }
}

// ---------------- fp32 -> bf16 hi/lo split (vectorized) --------------------------
__global__ __launch_bounds__(256) void split_kernel(const float* __restrict__ src,
                                                    __nv_bfloat16* __restrict__ hi,
                                                    __nv_bfloat16* __restrict__ lo,
                                                    int n4) {
    int i = blockIdx.x * blockDim.x + threadIdx.x;
    if (i >= n4) return;
    float4 v = ((const float4*)src)[i];
    __nv_bfloat16 hx = __float2bfloat16(v.x);
    __nv_bfloat16 hy = __float2bfloat16(v.y);
    __nv_bfloat16 hz = __float2bfloat16(v.z);
    __nv_bfloat16 hw = __float2bfloat16(v.w);
    __nv_bfloat162* hp = (__nv_bfloat162*)hi;
    __nv_bfloat162* lp = (__nv_bfloat162*)lo;
    hp[2 * i + 0] = __nv_bfloat162{hx, hy};
    hp[2 * i + 1] = __nv_bfloat162{hz, hw};
    lp[2 * i + 0] = __nv_bfloat162{__float2bfloat16(v.x - __bfloat162float(hx)),
                                   __float2bfloat16(v.y - __bfloat162float(hy))};
    lp[2 * i + 1] = __nv_bfloat162{__float2bfloat16(v.z - __bfloat162float(hz)),
                                   __float2bfloat16(v.w - __bfloat162float(hw))};
}

// ---------------- split + per-head-row norm/scale --------------------------------
// Q/K [ROWS, DD] fp32 viewed as [MR2, 64] head-rows. Produces bf16 hi/lo splits
// and scale[row] = exp(-|q|^2/2)/16 (exact fp32 norm).
__global__ __launch_bounds__(256) void split_norm(const float* __restrict__ src,
                                                  __nv_bfloat16* __restrict__ hi,
                                                  __nv_bfloat16* __restrict__ lo,
                                                  float* __restrict__ scale) {
    const int gidx = blockIdx.x * blockDim.x + threadIdx.x;   // one float4 each
    float4 v = ((const float4*)src)[gidx];
    float ns = v.x * v.x + v.y * v.y + v.z * v.z + v.w * v.w;
#pragma unroll
    for (int m = 8; m >= 1; m >>= 1) ns += __shfl_xor_sync(0xffffffffu, ns, m);
    __nv_bfloat16 hx = __float2bfloat16(v.x);
    __nv_bfloat16 hy = __float2bfloat16(v.y);
    __nv_bfloat16 hz = __float2bfloat16(v.z);
    __nv_bfloat16 hw = __float2bfloat16(v.w);
    __nv_bfloat162* hp = (__nv_bfloat162*)hi;
    __nv_bfloat162* lp = (__nv_bfloat162*)lo;
    hp[2 * gidx + 0] = __nv_bfloat162{hx, hy};
    hp[2 * gidx + 1] = __nv_bfloat162{hz, hw};
    lp[2 * gidx + 0] = __nv_bfloat162{__float2bfloat16(v.x - __bfloat162float(hx)),
                                      __float2bfloat16(v.y - __bfloat162float(hy))};
    lp[2 * gidx + 1] = __nv_bfloat162{__float2bfloat16(v.z - __bfloat162float(hz)),
                                      __float2bfloat16(v.w - __bfloat162float(hw))};
    if ((gidx & 15) == 0)
        scale[gidx >> 4] = expf(-0.5f * ns) * 0.0625f;
}

// ---------------- phi GEMM: proj = A[MR2,64] x rf[256,64]^T, epilogue sincos -----
// A = head-row splits of Q/K; out feat[bh][t][512]: cos->m, sin->256+m, *scale.
// CTA tile 128(M) x 128(N of rf-rows), K=64 single stage. 8 warps, 64x32 per warp.
// Smem rows 128B (64 bf16), SW128 swizzle.
#define P_AHI 0
#define P_ALO 16384
#define P_BHI 32768
#define P_BLO 49152
#define P_SC  65536
#define P_TOTAL (P_SC + 512)

__global__ __launch_bounds__(256)
void phi_gemm(const __nv_bfloat16* __restrict__ Ahi, const __nv_bfloat16* __restrict__ Alo,
              const __nv_bfloat16* __restrict__ Bhi, const __nv_bfloat16* __restrict__ Blo,
              const float* __restrict__ scale, float* __restrict__ outF) {
    extern __shared__ char smem[];
    const uint32_t sbase = smem_u32(smem);
    float* scale_s = (float*)(smem + P_SC);
    const int tid = threadIdx.x;
    const int wid = tid >> 5, lane = tid & 31;
    const int warpM = (wid >> 2) * 64;
    const int warpN = (wid & 3) * 32;
    const int brow = blockIdx.y * 128;
    const int bcol = blockIdx.x * 128;

    // load tiles: 128 rows x 8 chunks(16B) per array; 1024 chunks/array
    for (int u = tid; u < 1024; u += 256) {
        const int row = u >> 3, c = u & 7;
        const uint32_t soff = SWZ128((uint32_t)(row * 128 + c * 16));
        const size_t ga = (size_t)(brow + row) * 64 + c * 8;
        const size_t gb = (size_t)(bcol + row) * 64 + c * 8;
        CP_ASYNC16(sbase + P_AHI + soff, Ahi + ga);
        CP_ASYNC16(sbase + P_ALO + soff, Alo + ga);
        CP_ASYNC16(sbase + P_BHI + soff, Bhi + gb);
        CP_ASYNC16(sbase + P_BLO + soff, Blo + gb);
    }
    CP_ASYNC_COMMIT();
    if (tid < 128) scale_s[tid] = scale[brow + tid];
    CP_ASYNC_WAIT0();
    __syncthreads();

    float acc[4][4][4];
#pragma unroll
    for (int i = 0; i < 4; i++)
#pragma unroll
        for (int j = 0; j < 4; j++)
#pragma unroll
            for (int r = 0; r < 4; r++) acc[i][j][r] = 0.f;

#pragma unroll
    for (int kk = 0; kk < 4; kk++) {          // 4 sub-chunks of k16 (32B each)
        uint32_t bh[4][2], bl[4][2];
#pragma unroll
        for (int ni = 0; ni < 4; ni++) {
            const int n = warpN + ni * 8 + (lane & 7);
            const uint32_t bc = (uint32_t)(kk * 32 + ((lane >> 3) & 1) * 16);
            const uint32_t ad = sbase + P_BHI + SWZ128((uint32_t)(n * 128) + bc);
            LDMATRIX_X2(bh[ni], ad);
            LDMATRIX_X2(bl[ni], ad + 16384);
        }
        uint32_t af[4][4];
#pragma unroll
        for (int mi = 0; mi < 4; mi++) {
            const int m = warpM + mi * 16 + (lane & 15);
            const uint32_t bc = (uint32_t)(kk * 32 + (lane >> 4) * 16);
            const uint32_t ad = sbase + P_AHI + SWZ128((uint32_t)(m * 128) + bc);
            LDMATRIX_X4(af[mi], ad);
        }
#pragma unroll
        for (int mi = 0; mi < 4; mi++)
#pragma unroll
            for (int ni = 0; ni < 4; ni++) MMA16816(acc[mi][ni], af[mi], bh[ni]);
#pragma unroll
        for (int mi = 0; mi < 4; mi++)
#pragma unroll
            for (int ni = 0; ni < 4; ni++) MMA16816(acc[mi][ni], af[mi], bl[ni]);
#pragma unroll
        for (int mi = 0; mi < 4; mi++) {
            const int m = warpM + mi * 16 + (lane & 15);
            const uint32_t bc = (uint32_t)(kk * 32 + (lane >> 4) * 16);
            const uint32_t ad = sbase + P_ALO + SWZ128((uint32_t)(m * 128) + bc);
            LDMATRIX_X4(af[mi], ad);
        }
#pragma unroll
        for (int mi = 0; mi < 4; mi++)
#pragma unroll
            for (int ni = 0; ni < 4; ni++) MMA16816(acc[mi][ni], af[mi], bh[ni]);
    }

    // ---- epilogue: sincos + scale + scatter into feat layout ----
#pragma unroll
    for (int mi = 0; mi < 4; mi++) {
#pragma unroll
        for (int rr = 0; rr < 2; rr++) {
            const int lrow = warpM + mi * 16 + (lane >> 2) + rr * 8;
            const int grow = brow + lrow;                      // (b*TT+t)*16 + h
            const float sc = scale_s[lrow];
            const int b = grow >> 16;                          // / (TT*16)
            const int rem = grow & 65535;
            const int t = rem >> 4;
            const int h = rem & 15;
            float* obase = outF + ((size_t)((b << 4) + h) * TT + t) * FD;
#pragma unroll
            for (int ni = 0; ni < 4; ni++) {
                const int m0 = bcol + warpN + ni * 8 + (lane & 3) * 2;
                float s0, c0, s1, c1;
                __sincosf(acc[mi][ni][rr * 2 + 0], &s0, &c0);
                __sincosf(acc[mi][ni][rr * 2 + 1], &s1, &c1);
                *(float2*)(obase + m0)       = make_float2(c0 * sc, c1 * sc);
                *(float2*)(obase + 256 + m0) = make_float2(s0 * sc, s1 * sc);
            }
        }
    }
}

// ---------------- KV partial ------------------------------------------------------
__global__ __launch_bounds__(512, 1) void kv_kernel(const float* __restrict__ Kf,
                                                    const float* __restrict__ V,
                                                    float* __restrict__ part) {
    __shared__ float Vs[32][64];
    const int tid = threadIdx.x;                 // tid == f
    const int bh = blockIdx.y, b = bh >> 4, h = bh & 15;
    const int split = blockIdx.x;
    const int tbase = split * (TT / NSPLIT);     // 256 t per block
    float acc[65];
#pragma unroll
    for (int d = 0; d < 65; d++) acc[d] = 0.f;

    for (int tc0 = 0; tc0 < TT / NSPLIT; tc0 += 32) {
        __syncthreads();
        for (int i = tid; i < 32 * 64; i += 512) {
            int t = i >> 6, d = i & 63;
            Vs[t][d] = V[(size_t)(b * TT + tbase + tc0 + t) * DD + h * DH + d];
        }
        __syncthreads();
        const float* kfp = Kf + ((size_t)bh * TT + tbase + tc0) * FD + tid;
        float kf_next = kfp[0];
#pragma unroll 4
        for (int t = 0; t < 32; t++) {
            float kf = kf_next;
            if (t < 31) kf_next = kfp[(size_t)(t + 1) * FD];
#pragma unroll
            for (int d = 0; d < 64; d += 4) {
                float4 v = *(const float4*)&Vs[t][d];
                acc[d + 0] = fmaf(kf, v.x, acc[d + 0]);
                acc[d + 1] = fmaf(kf, v.y, acc[d + 1]);
                acc[d + 2] = fmaf(kf, v.z, acc[d + 2]);
                acc[d + 3] = fmaf(kf, v.w, acc[d + 3]);
            }
            acc[64] += kf;
        }
    }
    float* p = part + (((size_t)bh * NSPLIT + split) * FD + tid) * 65;
#pragma unroll
    for (int d = 0; d < 65; d++) p[d] = acc[d];
}

// ---------------- deterministic reduce over splits -------------------------------
__global__ void kv_reduce(const float* __restrict__ part, float* __restrict__ KV) {
    const int bh = blockIdx.x;
    for (int i = threadIdx.x; i < FD * 65; i += blockDim.x) {
        float s = 0.f;
#pragma unroll
        for (int p = 0; p < NSPLIT; p++)
            s += part[((size_t)bh * NSPLIT + p) * FD * 65 + i];
        KV[(size_t)bh * FD * 65 + i] = s;
    }
}

// ---------------- QKV + Z + normalize --------------------------------------------
__global__ __launch_bounds__(256) void qkv_kernel(const float* __restrict__ Qf,
                                                  const float* __restrict__ KV,
                                                  float* __restrict__ attn) {
    __shared__ float Qfs[16][64];
    __shared__ float KVs[16][64];
    __shared__ float ksums[16];
    __shared__ float zs[64];
    const int tid = threadIdx.x;
    const int bh = blockIdx.y, b = bh >> 4, h = bh & 15;
    const int t0 = blockIdx.x * 64;
    const int ty = tid >> 4, tx = tid & 15;
    float acc[4][4];
#pragma unroll
    for (int i = 0; i < 4; i++)
#pragma unroll
        for (int j = 0; j < 4; j++) acc[i][j] = 0.f;
    float zacc = 0.f;

    for (int f0 = 0; f0 < FD; f0 += 16) {
        __syncthreads();
        for (int i = tid; i < 1024; i += 256) {
            int t = i >> 4, kk = i & 15;
            Qfs[kk][t] = Qf[((size_t)bh * TT + t0 + t) * FD + f0 + kk];
        }
        for (int i = tid; i < 1024; i += 256) {
            int kk = i >> 6, d = i & 63;
            KVs[kk][d] = KV[((size_t)bh * FD + f0 + kk) * 65 + d];
        }
        if (tid < 16) ksums[tid] = KV[((size_t)bh * FD + f0 + tid) * 65 + 64];
        __syncthreads();
#pragma unroll
        for (int kk = 0; kk < 16; kk++) {
            float4 a  = *(const float4*)&Qfs[kk][ty * 4];
            float4 bb = *(const float4*)&KVs[kk][tx * 4];
            float av[4] = {a.x, a.y, a.z, a.w};
            float bv[4] = {bb.x, bb.y, bb.z, bb.w};
#pragma unroll
            for (int i = 0; i < 4; i++)
#pragma unroll
                for (int j = 0; j < 4; j++)
                    acc[i][j] = fmaf(av[i], bv[j], acc[i][j]);
        }
        if (tid < 64) {
#pragma unroll
            for (int kk = 0; kk < 16; kk++)
                zacc = fmaf(Qfs[kk][tid], ksums[kk], zacc);
        }
    }
    __syncthreads();
    if (tid < 64) zs[tid] = fmaxf(zacc, 1e-6f);
    __syncthreads();
#pragma unroll
    for (int i = 0; i < 4; i++) {
        int t = ty * 4 + i;
        float invz = 1.f / zs[t];
        float4 o = make_float4(acc[i][0] * invz, acc[i][1] * invz,
                               acc[i][2] * invz, acc[i][3] * invz);
        *(float4*)(attn + (size_t)(b * TT + t0 + t) * DD + h * DH + tx * 4) = o;
    }
}

// ---------------- launch ----------------------------------------------------------
extern "C" void kernel_launch(void* const* d_in, const int* in_sizes, int n_in,
                              void* d_out, int out_size) {
    (void)in_sizes; (void)n_in; (void)out_size;
    const float* x  = (const float*)d_in[0];
    const float* wq = (const float*)d_in[1];
    const float* wk = (const float*)d_in[2];
    const float* wv = (const float*)d_in[3];
    const float* wo = (const float*)d_in[4];
    const float* rf = (const float*)d_in[5];
    float* out = (float*)d_out;

    float *Q, *K, *V, *Qf, *Kf, *attn, *part, *KV, *scl;
    __nv_bfloat16 *Ahi, *Alo, *Whi, *Wlo;
    cudaGetSymbolAddress((void**)&Q,    g_Q);
    cudaGetSymbolAddress((void**)&K,    g_K);
    cudaGetSymbolAddress((void**)&V,    g_V);
    cudaGetSymbolAddress((void**)&Qf,   g_Qf);
    cudaGetSymbolAddress((void**)&Kf,   g_Kf);
    cudaGetSymbolAddress((void**)&attn, g_attn);
    cudaGetSymbolAddress((void**)&part, g_KVpart);
    cudaGetSymbolAddress((void**)&KV,   g_KV);
    cudaGetSymbolAddress((void**)&scl,  g_scale);
    cudaGetSymbolAddress((void**)&Ahi,  g_Ahi);
    cudaGetSymbolAddress((void**)&Alo,  g_Alo);
    cudaGetSymbolAddress((void**)&Whi,  g_Whi);
    cudaGetSymbolAddress((void**)&Wlo,  g_Wlo);

    cudaFuncSetAttribute(gemm_tc, cudaFuncAttributeMaxDynamicSharedMemorySize, G_TOTAL);
    cudaFuncSetAttribute(phi_gemm, cudaFuncAttributeMaxDynamicSharedMemorySize, P_TOTAL);

    const int nX4 = ROWS * DD / 4;   // 2097152
    const int nW4 = DD * DD / 4;     // 262144
    dim3 gg(DD / 128, ROWS / 128);   // (8, 64)

    // x split once, reused by the 3 projections
    split_kernel<<<nX4 / 256, 256>>>(x, Ahi, Alo, nX4);

    split_kernel<<<nW4 / 256, 256>>>(wq, Whi, Wlo, nW4);
    gemm_tc<<<gg, 256, G_TOTAL>>>(Ahi, Alo, Whi, Wlo, Q, ROWS, DD, DD);
    split_kernel<<<nW4 / 256, 256>>>(wk, Whi, Wlo, nW4);
    gemm_tc<<<gg, 256, G_TOTAL>>>(Ahi, Alo, Whi, Wlo, K, ROWS, DD, DD);
    split_kernel<<<nW4 / 256, 256>>>(wv, Whi, Wlo, nW4);
    gemm_tc<<<gg, 256, G_TOTAL>>>(Ahi, Alo, Whi, Wlo, V, ROWS, DD, DD);

    // rf split (reuses W split buffers; rf = [256,64])
    split_kernel<<<16, 256>>>(rf, Whi, Wlo, 256 * 64 / 4);

    // phi via HMMA: Q then K (reuse A split buffers)
    dim3 gp(2, MR2 / 128);           // (2, 1024)
    split_norm<<<MR2 * 16 / 256, 256>>>(Q, Ahi, Alo, scl);
    phi_gemm<<<gp, 256, P_TOTAL>>>(Ahi, Alo, Whi, Wlo, scl, Qf);
    split_norm<<<MR2 * 16 / 256, 256>>>(K, Ahi, Alo, scl);
    phi_gemm<<<gp, 256, P_TOTAL>>>(Ahi, Alo, Whi, Wlo, scl, Kf);

    kv_kernel<<<dim3(NSPLIT, BHN), 512>>>(Kf, V, part);
    kv_reduce<<<BHN, 256>>>(part, KV);

    qkv_kernel<<<dim3(TT / 64, BHN), 256>>>(Qf, KV, attn);

    // output projection: attn reuses the A-split buffers
    split_kernel<<<nX4 / 256, 256>>>(attn, Ahi, Alo, nX4);
    split_kernel<<<nW4 / 256, 256>>>(wo, Whi, Wlo, nW4);
    gemm_tc<<<gg, 256, G_TOTAL>>>(Ahi, Alo, Whi, Wlo, out, ROWS, DD, DD);
}

// round 8
// speedup vs baseline: 1.8857x; 1.8857x over previous
#include <cuda_runtime.h>
#include <cuda_bf16.h>
#include <cstdint>

#define TT  4096     // T
#define DD  1024     // D
#define HH  16
#define DH  64
#define BHN 32       // B*H
#define ROWS 8192    // B*T
#define FD  512      // 2m
#define MR2 (ROWS * HH)   // 131072 head-rows

// ---------------- scratch (device globals; no runtime allocation) ----------------
__device__ float g_Q[ROWS * DD];
__device__ float g_K[ROWS * DD];
__device__ float g_V[ROWS * DD];
__device__ float g_attn[ROWS * DD];
__device__ float g_part[512 * 8192 + 512 * 128];     // KV partials + ksum partials
__device__ float g_scale[MR2];
__device__ __nv_bfloat16 g_Ahi[ROWS * DD];
__device__ __nv_bfloat16 g_Alo[ROWS * DD];
__device__ __nv_bfloat16 g_Whi[DD * DD];
__device__ __nv_bfloat16 g_Wlo[DD * DD];
__device__ __nv_bfloat16 g_Qfh[BHN * TT * FD];
__device__ __nv_bfloat16 g_Qfl[BHN * TT * FD];
__device__ __nv_bfloat16 g_Kfh[BHN * TT * FD];
__device__ __nv_bfloat16 g_Kfl[BHN * TT * FD];
__device__ __nv_bfloat16 g_Vhi[ROWS * DD];
__device__ __nv_bfloat16 g_Vlo[ROWS * DD];
__device__ __nv_bfloat16 g_KVThi[BHN * 72 * FD];
__device__ __nv_bfloat16 g_KVTlo[BHN * 72 * FD];

#define KS_OFF (512 * 8192)

// =================== base-target PTX helpers (no tcgen05!) =======================
__device__ __forceinline__ uint32_t smem_u32(const void* p) {
    uint32_t a;
    asm("{ .reg .u64 t; cvta.to.shared.u64 t, %1; cvt.u32.u64 %0, t; }" : "=r"(a) : "l"(p));
    return a;
}
#define CP_ASYNC16(saddr, gptr) \
    asm volatile("cp.async.cg.shared.global [%0], [%1], 16;" :: "r"(saddr), "l"(gptr))
#define CP_ASYNC_COMMIT() asm volatile("cp.async.commit_group;" ::: "memory")
#define CP_ASYNC_WAIT1()  asm volatile("cp.async.wait_group 1;" ::: "memory")
#define CP_ASYNC_WAIT0()  asm volatile("cp.async.wait_group 0;" ::: "memory")
#define LDMATRIX_X4(r, addr) \
    asm volatile("ldmatrix.sync.aligned.m8n8.x4.shared.b16 {%0,%1,%2,%3}, [%4];" \
        : "=r"((r)[0]), "=r"((r)[1]), "=r"((r)[2]), "=r"((r)[3]) : "r"(addr))
#define LDMATRIX_X2(r, addr) \
    asm volatile("ldmatrix.sync.aligned.m8n8.x2.shared.b16 {%0,%1}, [%2];" \
        : "=r"((r)[0]), "=r"((r)[1]) : "r"(addr))
#define LDMATRIX_X4_TRANS(r, addr) \
    asm volatile("ldmatrix.sync.aligned.m8n8.x4.trans.shared.b16 {%0,%1,%2,%3}, [%4];" \
        : "=r"((r)[0]), "=r"((r)[1]), "=r"((r)[2]), "=r"((r)[3]) : "r"(addr))
#define LDMATRIX_X2_TRANS(r, addr) \
    asm volatile("ldmatrix.sync.aligned.m8n8.x2.trans.shared.b16 {%0,%1}, [%2];" \
        : "=r"((r)[0]), "=r"((r)[1]) : "r"(addr))
#define MMA16816(c, a, b) \
    asm volatile("mma.sync.aligned.m16n8k16.row.col.f32.bf16.bf16.f32 " \
        "{%0,%1,%2,%3}, {%4,%5,%6,%7}, {%8,%9}, {%0,%1,%2,%3};" \
        : "+f"((c)[0]), "+f"((c)[1]), "+f"((c)[2]), "+f"((c)[3]) \
        : "r"((a)[0]), "r"((a)[1]), "r"((a)[2]), "r"((a)[3]), "r"((b)[0]), "r"((b)[1]))
#define SWZ128(off) ((off) ^ (((off) >> 3) & 0x70))

// =================== HMMA bf16x3 split GEMM (big projections) ====================
#define G_STAGE 32768
#define G_AHI 0
#define G_ALO 8192
#define G_BHI 16384
#define G_BLO 24576
#define G_TOTAL (2 * G_STAGE)

__global__ __launch_bounds__(256)
void gemm_tc(const __nv_bfloat16* __restrict__ Ahi, const __nv_bfloat16* __restrict__ Alo,
             const __nv_bfloat16* __restrict__ Bhi, const __nv_bfloat16* __restrict__ Blo,
             float* __restrict__ C, int M, int N, int K) {
    extern __shared__ char smem[];
    const uint32_t sbase = smem_u32(smem);
    const int tid = threadIdx.x;
    const int wid = tid >> 5, lane = tid & 31;
    const int warpM = (wid >> 2) * 64;
    const int warpN = (wid & 3) * 32;
    const int brow = blockIdx.y * 128;
    const int bcol = blockIdx.x * 128;

    float acc[4][4][4];
#pragma unroll
    for (int i = 0; i < 4; i++)
#pragma unroll
        for (int j = 0; j < 4; j++)
#pragma unroll
            for (int r = 0; r < 4; r++) acc[i][j][r] = 0.f;

    const int r0 = tid >> 2, c0 = tid & 3;
    const int r1 = (tid + 256) >> 2, c1 = c0;
    const uint32_t so0 = (uint32_t)(r0 * 64 + ((c0 ^ ((r0 >> 1) & 3)) * 16));
    const uint32_t so1 = (uint32_t)(r1 * 64 + ((c1 ^ ((r1 >> 1) & 3)) * 16));

    const int nchunk = K >> 5;

#define ISSUE_CHUNK(ch, stg) do { \
    const int _k0 = (ch) << 5; \
    const uint32_t _st = sbase + (stg) * G_STAGE; \
    const size_t _ga0 = (size_t)(brow + r0) * K + _k0 + c0 * 8; \
    const size_t _ga1 = (size_t)(brow + r1) * K + _k0 + c1 * 8; \
    const size_t _gb0 = (size_t)(bcol + r0) * K + _k0 + c0 * 8; \
    const size_t _gb1 = (size_t)(bcol + r1) * K + _k0 + c1 * 8; \
    CP_ASYNC16(_st + G_AHI + so0, Ahi + _ga0); \
    CP_ASYNC16(_st + G_AHI + so1, Ahi + _ga1); \
    CP_ASYNC16(_st + G_ALO + so0, Alo + _ga0); \
    CP_ASYNC16(_st + G_ALO + so1, Alo + _ga1); \
    CP_ASYNC16(_st + G_BHI + so0, Bhi + _gb0); \
    CP_ASYNC16(_st + G_BHI + so1, Bhi + _gb1); \
    CP_ASYNC16(_st + G_BLO + so0, Blo + _gb0); \
    CP_ASYNC16(_st + G_BLO + so1, Blo + _gb1); \
    CP_ASYNC_COMMIT(); \
} while (0)

    ISSUE_CHUNK(0, 0);

    for (int ch = 0; ch < nchunk; ch++) {
        const int s = ch & 1;
        if (ch + 1 < nchunk) { ISSUE_CHUNK(ch + 1, s ^ 1); CP_ASYNC_WAIT1(); }
        else                 { CP_ASYNC_WAIT0(); }
        __syncthreads();

        const uint32_t st = sbase + s * G_STAGE;
#pragma unroll
        for (int kk = 0; kk < 2; kk++) {
            const int cb = kk * 2;
            uint32_t bh[4][2], bl[4][2];
#pragma unroll
            for (int ni = 0; ni < 4; ni++) {
                const int n = warpN + ni * 8 + (lane & 7);
                const int chk = cb + ((lane >> 3) & 1);
                const uint32_t ad = st + G_BHI + (uint32_t)(n * 64 + ((chk ^ ((n >> 1) & 3)) * 16));
                LDMATRIX_X2(bh[ni], ad);
                LDMATRIX_X2(bl[ni], ad + 8192);
            }
            uint32_t af[4][4];
#pragma unroll
            for (int mi = 0; mi < 4; mi++) {
                const int m = warpM + mi * 16 + (lane & 15);
                const int chk = cb + (lane >> 4);
                const uint32_t ad = st + G_AHI + (uint32_t)(m * 64 + ((chk ^ ((m >> 1) & 3)) * 16));
                LDMATRIX_X4(af[mi], ad);
            }
#pragma unroll
            for (int mi = 0; mi < 4; mi++)
#pragma unroll
                for (int ni = 0; ni < 4; ni++) MMA16816(acc[mi][ni], af[mi], bh[ni]);
#pragma unroll
            for (int mi = 0; mi < 4; mi++)
#pragma unroll
                for (int ni = 0; ni < 4; ni++) MMA16816(acc[mi][ni], af[mi], bl[ni]);
#pragma unroll
            for (int mi = 0; mi < 4; mi++) {
                const int m = warpM + mi * 16 + (lane & 15);
                const int chk = cb + (lane >> 4);
                const uint32_t ad = st + G_ALO + (uint32_t)(m * 64 + ((chk ^ ((m >> 1) & 3)) * 16));
                LDMATRIX_X4(af[mi], ad);
            }
#pragma unroll
            for (int mi = 0; mi < 4; mi++)
#pragma unroll
                for (int ni = 0; ni < 4; ni++) MMA16816(acc[mi][ni], af[mi], bh[ni]);
        }
        __syncthreads();
    }
#undef ISSUE_CHUNK

#pragma unroll
    for (int mi = 0; mi < 4; mi++) {
        const int row = brow + warpM + mi * 16 + (lane >> 2);
#pragma unroll
        for (int ni = 0; ni < 4; ni++) {
            const int col = bcol + warpN + ni * 8 + (lane & 3) * 2;
            *(float2*)(C + (size_t)row * N + col)       = make_float2(acc[mi][ni][0], acc[mi][ni][1]);
            *(float2*)(C + (size_t)(row + 8) * N + col) = make_float2(acc[mi][ni][2], acc[mi][ni][3]);
        }
    }
}

// ---------------- fp32 -> bf16 hi/lo split (vectorized) --------------------------
__global__ __launch_bounds__(256) void split_kernel(const float* __restrict__ src,
                                                    __nv_bfloat16* __restrict__ hi,
                                                    __nv_bfloat16* __restrict__ lo,
                                                    int n4) {
    int i = blockIdx.x * blockDim.x + threadIdx.x;
    if (i >= n4) return;
    float4 v = ((const float4*)src)[i];
    __nv_bfloat16 hx = __float2bfloat16(v.x);
    __nv_bfloat16 hy = __float2bfloat16(v.y);
    __nv_bfloat16 hz = __float2bfloat16(v.z);
    __nv_bfloat16 hw = __float2bfloat16(v.w);
    __nv_bfloat162* hp = (__nv_bfloat162*)hi;
    __nv_bfloat162* lp = (__nv_bfloat162*)lo;
    hp[2 * i + 0] = __nv_bfloat162{hx, hy};
    hp[2 * i + 1] = __nv_bfloat162{hz, hw};
    lp[2 * i + 0] = __nv_bfloat162{__float2bfloat16(v.x - __bfloat162float(hx)),
                                   __float2bfloat16(v.y - __bfloat162float(hy))};
    lp[2 * i + 1] = __nv_bfloat162{__float2bfloat16(v.z - __bfloat162float(hz)),
                                   __float2bfloat16(v.w - __bfloat162float(hw))};
}

// ---------------- split + per-head-row norm/scale --------------------------------
__global__ __launch_bounds__(256) void split_norm(const float* __restrict__ src,
                                                  __nv_bfloat16* __restrict__ hi,
                                                  __nv_bfloat16* __restrict__ lo,
                                                  float* __restrict__ scale) {
    const int gidx = blockIdx.x * blockDim.x + threadIdx.x;
    float4 v = ((const float4*)src)[gidx];
    float ns = v.x * v.x + v.y * v.y + v.z * v.z + v.w * v.w;
#pragma unroll
    for (int m = 8; m >= 1; m >>= 1) ns += __shfl_xor_sync(0xffffffffu, ns, m);
    __nv_bfloat16 hx = __float2bfloat16(v.x);
    __nv_bfloat16 hy = __float2bfloat16(v.y);
    __nv_bfloat16 hz = __float2bfloat16(v.z);
    __nv_bfloat16 hw = __float2bfloat16(v.w);
    __nv_bfloat162* hp = (__nv_bfloat162*)hi;
    __nv_bfloat162* lp = (__nv_bfloat162*)lo;
    hp[2 * gidx + 0] = __nv_bfloat162{hx, hy};
    hp[2 * gidx + 1] = __nv_bfloat162{hz, hw};
    lp[2 * gidx + 0] = __nv_bfloat162{__float2bfloat16(v.x - __bfloat162float(hx)),
                                      __float2bfloat16(v.y - __bfloat162float(hy))};
    lp[2 * gidx + 1] = __nv_bfloat162{__float2bfloat16(v.z - __bfloat162float(hz)),
                                      __float2bfloat16(v.w - __bfloat162float(hw))};
    if ((gidx & 15) == 0)
        scale[gidx >> 4] = expf(-0.5f * ns) * 0.0625f;
}

// ---------------- phi GEMM + staged bf16 hi/lo output ----------------------------
// proj = A[MR2,64] x rf[256,64]^T; out: cos->cols m, sin->cols 256+m, *scale.
// Outputs bf16 hi/lo feature buffers [bh][t][512] with coalesced staged writes.
#define P_AHI 0
#define P_ALO 16384
#define P_BHI 32768
#define P_BLO 49152
#define P_SC  65536
#define P_TOTAL (P_SC + 512)

__global__ __launch_bounds__(256)
void phi_gemm(const __nv_bfloat16* __restrict__ Ahi, const __nv_bfloat16* __restrict__ Alo,
              const __nv_bfloat16* __restrict__ Bhi, const __nv_bfloat16* __restrict__ Blo,
              const float* __restrict__ scale,
              __nv_bfloat16* __restrict__ outH, __nv_bfloat16* __restrict__ outL) {
    extern __shared__ char smem[];
    const uint32_t sbase = smem_u32(smem);
    float* scale_s = (float*)(smem + P_SC);
    const int tid = threadIdx.x;
    const int wid = tid >> 5, lane = tid & 31;
    const int warpM = (wid >> 2) * 64;
    const int warpN = (wid & 3) * 32;
    const int brow = blockIdx.y * 128;
    const int bcol = blockIdx.x * 128;

    for (int u = tid; u < 1024; u += 256) {
        const int row = u >> 3, c = u & 7;
        const uint32_t soff = SWZ128((uint32_t)(row * 128 + c * 16));
        const size_t ga = (size_t)(brow + row) * 64 + c * 8;
        const size_t gb = (size_t)(bcol + row) * 64 + c * 8;
        CP_ASYNC16(sbase + P_AHI + soff, Ahi + ga);
        CP_ASYNC16(sbase + P_ALO + soff, Alo + ga);
        CP_ASYNC16(sbase + P_BHI + soff, Bhi + gb);
        CP_ASYNC16(sbase + P_BLO + soff, Blo + gb);
    }
    CP_ASYNC_COMMIT();
    if (tid < 128) scale_s[tid] = scale[brow + tid];
    CP_ASYNC_WAIT0();
    __syncthreads();

    float acc[4][4][4];
#pragma unroll
    for (int i = 0; i < 4; i++)
#pragma unroll
        for (int j = 0; j < 4; j++)
#pragma unroll
            for (int r = 0; r < 4; r++) acc[i][j][r] = 0.f;

#pragma unroll
    for (int kk = 0; kk < 4; kk++) {
        uint32_t bh[4][2], bl[4][2];
#pragma unroll
        for (int ni = 0; ni < 4; ni++) {
            const int n = warpN + ni * 8 + (lane & 7);
            const uint32_t bc = (uint32_t)(kk * 32 + ((lane >> 3) & 1) * 16);
            const uint32_t ad = sbase + P_BHI + SWZ128((uint32_t)(n * 128) + bc);
            LDMATRIX_X2(bh[ni], ad);
            LDMATRIX_X2(bl[ni], ad + 16384);
        }
        uint32_t af[4][4];
#pragma unroll
        for (int mi = 0; mi < 4; mi++) {
            const int m = warpM + mi * 16 + (lane & 15);
            const uint32_t bc = (uint32_t)(kk * 32 + (lane >> 4) * 16);
            const uint32_t ad = sbase + P_AHI + SWZ128((uint32_t)(m * 128) + bc);
            LDMATRIX_X4(af[mi], ad);
        }
#pragma unroll
        for (int mi = 0; mi < 4; mi++)
#pragma unroll
            for (int ni = 0; ni < 4; ni++) MMA16816(acc[mi][ni], af[mi], bh[ni]);
#pragma unroll
        for (int mi = 0; mi < 4; mi++)
#pragma unroll
            for (int ni = 0; ni < 4; ni++) MMA16816(acc[mi][ni], af[mi], bl[ni]);
#pragma unroll
        for (int mi = 0; mi < 4; mi++) {
            const int m = warpM + mi * 16 + (lane & 15);
            const uint32_t bc = (uint32_t)(kk * 32 + (lane >> 4) * 16);
            const uint32_t ad = sbase + P_ALO + SWZ128((uint32_t)(m * 128) + bc);
            LDMATRIX_X4(af[mi], ad);
        }
#pragma unroll
        for (int mi = 0; mi < 4; mi++)
#pragma unroll
            for (int ni = 0; ni < 4; ni++) MMA16816(acc[mi][ni], af[mi], bh[ni]);
    }

    // ---- staged epilogue: 4 passes (cos/sin x hi/lo), coalesced writes ----
    // stage layout: [128 rows][136 bf16] (padded)
    const int orow = tid >> 1, ohalf = tid & 1;
    const int grow = brow + orow;
    const int b = grow >> 16;
    const int rem = grow & 65535;
    const int t = rem >> 4;
    const int h = rem & 15;
    const size_t obase = ((size_t)(((b << 4) + h)) * TT + t) * FD;

#pragma unroll
    for (int pass = 0; pass < 4; pass++) {
        const bool iscos = (pass < 2);
        const bool ishi  = ((pass & 1) == 0);
        __syncthreads();
#pragma unroll
        for (int mi = 0; mi < 4; mi++) {
#pragma unroll
            for (int rr = 0; rr < 2; rr++) {
                const int row = warpM + mi * 16 + (lane >> 2) + rr * 8;
                const float sc = scale_s[row];
#pragma unroll
                for (int ni = 0; ni < 4; ni++) {
                    const int col = warpN + ni * 8 + (lane & 3) * 2;
                    float v0 = acc[mi][ni][rr * 2 + 0];
                    float v1 = acc[mi][ni][rr * 2 + 1];
                    v0 = (iscos ? __cosf(v0) : __sinf(v0)) * sc;
                    v1 = (iscos ? __cosf(v1) : __sinf(v1)) * sc;
                    if (!ishi) {
                        v0 = v0 - __bfloat162float(__float2bfloat16(v0));
                        v1 = v1 - __bfloat162float(__float2bfloat16(v1));
                    }
                    __nv_bfloat162 pk{__float2bfloat16(v0), __float2bfloat16(v1)};
                    *(__nv_bfloat162*)(smem + (size_t)(row * 136 + col) * 2) = pk;
                }
            }
        }
        __syncthreads();
        const int colbase = (iscos ? bcol : bcol + 256);
        char* dp = (char*)((ishi ? outH : outL) + obase + colbase + ohalf * 64);
        const char* sp = smem + orow * 272 + ohalf * 128;
#pragma unroll
        for (int j = 0; j < 16; j++)
            *(uint2*)(dp + j * 8) = *(const uint2*)(sp + j * 8);
    }
}

// =================== kv HMMA: C[f,d] = sum_t Kf[t,f] V[t,d] (+ ksum) =============
// grid: (x = ftile*4 + tsplit (16), y = bh (32)); block 256 (8 warps, f16 each).
#define KV_KHI 0
#define KV_KLO 8192
#define KV_VHI 16384
#define KV_VLO 20480
#define KV_STAGE 24576
#define KV_TOTAL (2 * KV_STAGE)

__global__ __launch_bounds__(256)
void kv_tc(const __nv_bfloat16* __restrict__ Kfh, const __nv_bfloat16* __restrict__ Kfl,
           const __nv_bfloat16* __restrict__ Vhi, const __nv_bfloat16* __restrict__ Vlo,
           float* __restrict__ part) {
    extern __shared__ char smem[];
    const uint32_t sbase = smem_u32(smem);
    const int tid = threadIdx.x, wid = tid >> 5, lane = tid & 31;
    const int bh = blockIdx.y, b = bh >> 4, h = bh & 15;
    const int ftile = blockIdx.x >> 2, tsplit = blockIdx.x & 3;
    const int warpM = wid * 16;
    const int fbase = ftile * 128;
    const size_t tb0 = (size_t)bh * TT + tsplit * 1024;
    const size_t vb0 = (size_t)b * TT + tsplit * 1024;

    float acc[8][4];
#pragma unroll
    for (int i = 0; i < 8; i++)
#pragma unroll
        for (int r = 0; r < 4; r++) acc[i][r] = 0.f;
    float ks = 0.f;

    const int tA0 = tid >> 4, cA0 = tid & 15;
    const int tA1 = (tid + 256) >> 4;
    const uint32_t sA0 = (uint32_t)(tA0 * 256 + ((cA0 ^ (tA0 & 7)) * 16));
    const uint32_t sA1 = (uint32_t)(tA1 * 256 + ((cA0 ^ (tA1 & 7)) * 16));
    const int tV = tid >> 3, cV = tid & 7;
    const uint32_t sV = (uint32_t)(tV * 128 + ((cV ^ (tV & 7)) * 16));

#define KV_ISSUE(ch, stg) do { \
    const uint32_t _st = sbase + (stg) * KV_STAGE; \
    const size_t _t0 = tb0 + (ch) * 32; \
    const size_t _v0 = vb0 + (ch) * 32; \
    CP_ASYNC16(_st + KV_KHI + sA0, Kfh + (_t0 + tA0) * FD + fbase + cA0 * 8); \
    CP_ASYNC16(_st + KV_KHI + sA1, Kfh + (_t0 + tA1) * FD + fbase + cA0 * 8); \
    CP_ASYNC16(_st + KV_KLO + sA0, Kfl + (_t0 + tA0) * FD + fbase + cA0 * 8); \
    CP_ASYNC16(_st + KV_KLO + sA1, Kfl + (_t0 + tA1) * FD + fbase + cA0 * 8); \
    CP_ASYNC16(_st + KV_VHI + sV, Vhi + (_v0 + tV) * DD + h * 64 + cV * 8); \
    CP_ASYNC16(_st + KV_VLO + sV, Vlo + (_v0 + tV) * DD + h * 64 + cV * 8); \
    CP_ASYNC_COMMIT(); \
} while (0)

    KV_ISSUE(0, 0);
    for (int ch = 0; ch < 32; ch++) {
        const int s = ch & 1;
        if (ch + 1 < 32) { KV_ISSUE(ch + 1, s ^ 1); CP_ASYNC_WAIT1(); }
        else             { CP_ASYNC_WAIT0(); }
        __syncthreads();
        const uint32_t st = sbase + s * KV_STAGE;
        // ---- ksum from Kf tiles (f = tid>>1, t-half = tid&1) ----
        {
            const int f = tid >> 1, th = tid & 1;
            const int cf = f >> 3, fo = (f & 7) * 2;
            const char* base = smem + s * KV_STAGE;
#pragma unroll
            for (int j = 0; j < 16; j++) {
                const int t = th * 16 + j;
                const uint32_t off = (uint32_t)(t * 256 + ((cf ^ (t & 7)) * 16) + fo);
                ks += __bfloat162float(*(const __nv_bfloat16*)(base + KV_KHI + off))
                    + __bfloat162float(*(const __nv_bfloat16*)(base + KV_KLO + off));
            }
        }
#pragma unroll
        for (int kt = 0; kt < 2; kt++) {
            const int k0 = kt * 16;
            const int ttA = k0 + (lane & 7) + ((lane >> 4) & 1) * 8;
            const int ccA = (warpM >> 3) + ((lane >> 3) & 1);
            const uint32_t aoff = (uint32_t)(ttA * 256 + ((ccA ^ (ttA & 7)) * 16));
            uint32_t ah[4], al[4];
            LDMATRIX_X4_TRANS(ah, st + KV_KHI + aoff);
            LDMATRIX_X4_TRANS(al, st + KV_KLO + aoff);
            const int ttB = k0 + (lane & 7) + ((lane >> 3) & 1) * 8;
            uint32_t bhf[8][2], blf[8][2];
#pragma unroll
            for (int ni = 0; ni < 8; ni++) {
                const uint32_t boff = (uint32_t)(ttB * 128 + ((ni ^ (ttB & 7)) * 16));
                LDMATRIX_X2_TRANS(bhf[ni], st + KV_VHI + boff);
                LDMATRIX_X2_TRANS(blf[ni], st + KV_VLO + boff);
            }
#pragma unroll
            for (int ni = 0; ni < 8; ni++) MMA16816(acc[ni], ah, bhf[ni]);
#pragma unroll
            for (int ni = 0; ni < 8; ni++) MMA16816(acc[ni], ah, blf[ni]);
#pragma unroll
            for (int ni = 0; ni < 8; ni++) MMA16816(acc[ni], al, bhf[ni]);
        }
        __syncthreads();
    }
#undef KV_ISSUE

    const int pidx = (bh * 4 + ftile) * 4 + tsplit;
    float* pb = part + (size_t)pidx * 8192;
    const int r = warpM + (lane >> 2);
    const int cb = (lane & 3) * 2;
#pragma unroll
    for (int ni = 0; ni < 8; ni++) {
        *(float2*)(pb + r * 64 + ni * 8 + cb)       = make_float2(acc[ni][0], acc[ni][1]);
        *(float2*)(pb + (r + 8) * 64 + ni * 8 + cb) = make_float2(acc[ni][2], acc[ni][3]);
    }
    const float ko = __shfl_xor_sync(0xffffffffu, ks, 1);
    if ((tid & 1) == 0)
        part[KS_OFF + pidx * 128 + (tid >> 1)] = ks + ko;
}

// ---------------- reduce partials -> bf16 split transposed KVT -------------------
// KVT[bh][72][512]: rows 0-63 = KV[d][f], row 64 = ksum[f], rows 65-71 = 0.
__global__ __launch_bounds__(256) void kv_reduce2(const float* __restrict__ part,
                                                  __nv_bfloat16* __restrict__ KVThi,
                                                  __nv_bfloat16* __restrict__ KVTlo) {
    const int bh = blockIdx.x;
    const int tid = threadIdx.x;
    const size_t kb = (size_t)bh * 72 * FD;
    for (int idx = tid; idx < 64 * 512; idx += 256) {
        const int d = idx >> 9, f = idx & 511;
        const int ft = f >> 7, fl = f & 127;
        float v = 0.f;
#pragma unroll
        for (int ts = 0; ts < 4; ts++)
            v += part[(size_t)(((bh * 4 + ft) * 4 + ts)) * 8192 + fl * 64 + d];
        __nv_bfloat16 hi = __float2bfloat16(v);
        KVThi[kb + (size_t)d * FD + f] = hi;
        KVTlo[kb + (size_t)d * FD + f] = __float2bfloat16(v - __bfloat162float(hi));
    }
    for (int f = tid; f < 512; f += 256) {
        const int ft = f >> 7, fl = f & 127;
        float v = 0.f;
#pragma unroll
        for (int ts = 0; ts < 4; ts++)
            v += part[KS_OFF + ((bh * 4 + ft) * 4 + ts) * 128 + fl];
        __nv_bfloat16 hi = __float2bfloat16(v);
        KVThi[kb + (size_t)64 * FD + f] = hi;
        KVTlo[kb + (size_t)64 * FD + f] = __float2bfloat16(v - __bfloat162float(hi));
    }
    const __nv_bfloat16 z = __float2bfloat16(0.f);
    for (int idx = tid; idx < 7 * 512; idx += 256) {
        const int d = 65 + (idx >> 9), f = idx & 511;
        KVThi[kb + (size_t)d * FD + f] = z;
        KVTlo[kb + (size_t)d * FD + f] = z;
    }
}

// =================== qkv HMMA: out = (Qf x KVT^T)[:,0:64] / Z --------------------
// grid: (x = t-block (32), y = bh (32)); block 256: warps 4M(32 rows) x 2N.
#define QK_QHI 0
#define QK_QLO 8192
#define QK_BHI 16384
#define QK_BLO 20992
#define QK_STAGE 25600
#define QK_ZS (2 * QK_STAGE)
#define QK_TOTAL (QK_ZS + 512)

__global__ __launch_bounds__(256)
void qkv_tc(const __nv_bfloat16* __restrict__ Qfh, const __nv_bfloat16* __restrict__ Qfl,
            const __nv_bfloat16* __restrict__ KVThi, const __nv_bfloat16* __restrict__ KVTlo,
            float* __restrict__ attn) {
    extern __shared__ char smem[];
    const uint32_t sbase = smem_u32(smem);
    const int tid = threadIdx.x, wid = tid >> 5, lane = tid & 31;
    const int bh = blockIdx.y, b = bh >> 4, h = bh & 15;
    const int tb = blockIdx.x;
    const int warpM = (wid >> 1) * 32;
    const int nodd = wid & 1;
    const int ntiles = 5 - nodd;              // even: tiles 0-4, odd: 5-8
    const size_t qrow0 = (size_t)bh * TT + tb * 128;
    const size_t kvb = (size_t)bh * 72 * FD;

    float acc[2][5][4];
#pragma unroll
    for (int i = 0; i < 2; i++)
#pragma unroll
        for (int j = 0; j < 5; j++)
#pragma unroll
            for (int r = 0; r < 4; r++) acc[i][j][r] = 0.f;

    const int tQ0 = tid >> 2, cQ = tid & 3;
    const int tQ1 = (tid + 256) >> 2;
    const uint32_t sQ0 = (uint32_t)(tQ0 * 64 + ((cQ ^ ((tQ0 >> 1) & 3)) * 16));
    const uint32_t sQ1 = (uint32_t)(tQ1 * 64 + ((cQ ^ ((tQ1 >> 1) & 3)) * 16));
    const int dB0 = tid >> 2;                 // 0..63
    const int dB1 = (tid + 256) >> 2;         // 64..127 (valid < 72)
    const uint32_t sB0 = (uint32_t)(dB0 * 64 + ((cQ ^ ((dB0 >> 1) & 3)) * 16));
    const uint32_t sB1 = (uint32_t)(dB1 * 64 + ((cQ ^ ((dB1 >> 1) & 3)) * 16));

#define QK_ISSUE(fc, stg) do { \
    const uint32_t _st = sbase + (stg) * QK_STAGE; \
    const int _f0 = (fc) * 32; \
    CP_ASYNC16(_st + QK_QHI + sQ0, Qfh + (qrow0 + tQ0) * FD + _f0 + cQ * 8); \
    CP_ASYNC16(_st + QK_QHI + sQ1, Qfh + (qrow0 + tQ1) * FD + _f0 + cQ * 8); \
    CP_ASYNC16(_st + QK_QLO + sQ0, Qfl + (qrow0 + tQ0) * FD + _f0 + cQ * 8); \
    CP_ASYNC16(_st + QK_QLO + sQ1, Qfl + (qrow0 + tQ1) * FD + _f0 + cQ * 8); \
    CP_ASYNC16(_st + QK_BHI + sB0, KVThi + kvb + (size_t)dB0 * FD + _f0 + cQ * 8); \
    CP_ASYNC16(_st + QK_BLO + sB0, KVTlo + kvb + (size_t)dB0 * FD + _f0 + cQ * 8); \
    if (tid < 32) { \
        CP_ASYNC16(_st + QK_BHI + sB1, KVThi + kvb + (size_t)dB1 * FD + _f0 + cQ * 8); \
        CP_ASYNC16(_st + QK_BLO + sB1, KVTlo + kvb + (size_t)dB1 * FD + _f0 + cQ * 8); \
    } \
    CP_ASYNC_COMMIT(); \
} while (0)

    QK_ISSUE(0, 0);
    for (int fc = 0; fc < 16; fc++) {
        const int s = fc & 1;
        if (fc + 1 < 16) { QK_ISSUE(fc + 1, s ^ 1); CP_ASYNC_WAIT1(); }
        else             { CP_ASYNC_WAIT0(); }
        __syncthreads();
        const uint32_t st = sbase + s * QK_STAGE;
#pragma unroll
        for (int kc = 0; kc < 2; kc++) {
            uint32_t ahf[2][4], alf[2][4];
#pragma unroll
            for (int mi = 0; mi < 2; mi++) {
                const int tt = warpM + mi * 16 + (lane & 7) + ((lane >> 3) & 1) * 8;
                const int cc = kc * 2 + ((lane >> 4) & 1);
                const uint32_t aoff = (uint32_t)(tt * 64 + ((cc ^ ((tt >> 1) & 3)) * 16));
                LDMATRIX_X4(ahf[mi], st + QK_QHI + aoff);
                LDMATRIX_X4(alf[mi], st + QK_QLO + aoff);
            }
            uint32_t bhf[5][2], blf[5][2];
#pragma unroll
            for (int ni = 0; ni < 5; ni++) {
                if (ni < ntiles) {
                    const int gt = ni + nodd * 5;
                    const int dd = gt * 8 + (lane & 7);
                    const int cc = kc * 2 + ((lane >> 3) & 1);
                    const uint32_t boff = (uint32_t)(dd * 64 + ((cc ^ ((dd >> 1) & 3)) * 16));
                    LDMATRIX_X2(bhf[ni], st + QK_BHI + boff);
                    LDMATRIX_X2(blf[ni], st + QK_BLO + boff);
                }
            }
#pragma unroll
            for (int mi = 0; mi < 2; mi++)
#pragma unroll
                for (int ni = 0; ni < 5; ni++)
                    if (ni < ntiles) MMA16816(acc[mi][ni], ahf[mi], bhf[ni]);
#pragma unroll
            for (int mi = 0; mi < 2; mi++)
#pragma unroll
                for (int ni = 0; ni < 5; ni++)
                    if (ni < ntiles) MMA16816(acc[mi][ni], ahf[mi], blf[ni]);
#pragma unroll
            for (int mi = 0; mi < 2; mi++)
#pragma unroll
                for (int ni = 0; ni < 5; ni++)
                    if (ni < ntiles) MMA16816(acc[mi][ni], alf[mi], bhf[ni]);
        }
        __syncthreads();
    }
#undef QK_ISSUE

    // ---- Z broadcast (column 64 lives in odd warps, local ni=3) ----
    float* zsp = (float*)(smem + QK_ZS);
    if (nodd && (lane & 3) == 0) {
#pragma unroll
        for (int mi = 0; mi < 2; mi++) {
            const int r = warpM + mi * 16 + (lane >> 2);
            zsp[r] = acc[mi][3][0];
            zsp[r + 8] = acc[mi][3][2];
        }
    }
    __syncthreads();

    const size_t obase = ((size_t)b * TT + tb * 128) * DD + h * 64;
#pragma unroll
    for (int mi = 0; mi < 2; mi++) {
        const int r = warpM + mi * 16 + (lane >> 2);
        const float iz0 = 1.f / fmaxf(zsp[r], 1e-6f);
        const float iz1 = 1.f / fmaxf(zsp[r + 8], 1e-6f);
#pragma unroll
        for (int ni = 0; ni < 5; ni++) {
            if (ni < ntiles) {
                const int gt = ni + nodd * 5;
                if (gt == 8) continue;
                const int d = gt * 8 + (lane & 3) * 2;
                *(float2*)(attn + obase + (size_t)r * DD + d) =
                    make_float2(acc[mi][ni][0] * iz0, acc[mi][ni][1] * iz0);
                *(float2*)(attn + obase + (size_t)(r + 8) * DD + d) =
                    make_float2(acc[mi][ni][2] * iz1, acc[mi][ni][3] * iz1);
            }
        }
    }
}

// ---------------- launch ----------------------------------------------------------
extern "C" void kernel_launch(void* const* d_in, const int* in_sizes, int n_in,
                              void* d_out, int out_size) {
    (void)in_sizes; (void)n_in; (void)out_size;
    const float* x  = (const float*)d_in[0];
    const float* wq = (const float*)d_in[1];
    const float* wk = (const float*)d_in[2];
    const float* wv = (const float*)d_in[3];
    const float* wo = (const float*)d_in[4];
    const float* rf = (const float*)d_in[5];
    float* out = (float*)d_out;

    float *Q, *K, *V, *attn, *part, *scl;
    __nv_bfloat16 *Ahi, *Alo, *Whi, *Wlo, *Qfh, *Qfl, *Kfh, *Kfl, *Vhi, *Vlo, *KVThi, *KVTlo;
    cudaGetSymbolAddress((void**)&Q,     g_Q);
    cudaGetSymbolAddress((void**)&K,     g_K);
    cudaGetSymbolAddress((void**)&V,     g_V);
    cudaGetSymbolAddress((void**)&attn,  g_attn);
    cudaGetSymbolAddress((void**)&part,  g_part);
    cudaGetSymbolAddress((void**)&scl,   g_scale);
    cudaGetSymbolAddress((void**)&Ahi,   g_Ahi);
    cudaGetSymbolAddress((void**)&Alo,   g_Alo);
    cudaGetSymbolAddress((void**)&Whi,   g_Whi);
    cudaGetSymbolAddress((void**)&Wlo,   g_Wlo);
    cudaGetSymbolAddress((void**)&Qfh,   g_Qfh);
    cudaGetSymbolAddress((void**)&Qfl,   g_Qfl);
    cudaGetSymbolAddress((void**)&Kfh,   g_Kfh);
    cudaGetSymbolAddress((void**)&Kfl,   g_Kfl);
    cudaGetSymbolAddress((void**)&Vhi,   g_Vhi);
    cudaGetSymbolAddress((void**)&Vlo,   g_Vlo);
    cudaGetSymbolAddress((void**)&KVThi, g_KVThi);
    cudaGetSymbolAddress((void**)&KVTlo, g_KVTlo);

    cudaFuncSetAttribute(gemm_tc,  cudaFuncAttributeMaxDynamicSharedMemorySize, G_TOTAL);
    cudaFuncSetAttribute(phi_gemm, cudaFuncAttributeMaxDynamicSharedMemorySize, P_TOTAL);
    cudaFuncSetAttribute(kv_tc,    cudaFuncAttributeMaxDynamicSharedMemorySize, KV_TOTAL);
    cudaFuncSetAttribute(qkv_tc,   cudaFuncAttributeMaxDynamicSharedMemorySize, QK_TOTAL);

    const int nX4 = ROWS * DD / 4;
    const int nW4 = DD * DD / 4;
    dim3 gg(DD / 128, ROWS / 128);

    split_kernel<<<nX4 / 256, 256>>>(x, Ahi, Alo, nX4);

    split_kernel<<<nW4 / 256, 256>>>(wq, Whi, Wlo, nW4);
    gemm_tc<<<gg, 256, G_TOTAL>>>(Ahi, Alo, Whi, Wlo, Q, ROWS, DD, DD);
    split_kernel<<<nW4 / 256, 256>>>(wk, Whi, Wlo, nW4);
    gemm_tc<<<gg, 256, G_TOTAL>>>(Ahi, Alo, Whi, Wlo, K, ROWS, DD, DD);
    split_kernel<<<nW4 / 256, 256>>>(wv, Whi, Wlo, nW4);
    gemm_tc<<<gg, 256, G_TOTAL>>>(Ahi, Alo, Whi, Wlo, V, ROWS, DD, DD);

    // V split for HMMA kv
    split_kernel<<<nX4 / 256, 256>>>(V, Vhi, Vlo, nX4);

    // rf split (reuses W split buffers)
    split_kernel<<<16, 256>>>(rf, Whi, Wlo, 256 * 64 / 4);

    // phi via HMMA with staged bf16 hi/lo output
    dim3 gp(2, MR2 / 128);
    split_norm<<<MR2 * 16 / 256, 256>>>(Q, Ahi, Alo, scl);
    phi_gemm<<<gp, 256, P_TOTAL>>>(Ahi, Alo, Whi, Wlo, scl, Qfh, Qfl);
    split_norm<<<MR2 * 16 / 256, 256>>>(K, Ahi, Alo, scl);
    phi_gemm<<<gp, 256, P_TOTAL>>>(Ahi, Alo, Whi, Wlo, scl, Kfh, Kfl);

    // kv + reduce + qkv (all HMMA)
    kv_tc<<<dim3(16, BHN), 256, KV_TOTAL>>>(Kfh, Kfl, Vhi, Vlo, part);
    kv_reduce2<<<BHN, 256>>>(part, KVThi, KVTlo);
    qkv_tc<<<dim3(TT / 128, BHN), 256, QK_TOTAL>>>(Qfh, Qfl, KVThi, KVTlo, attn);

    // output projection
    split_kernel<<<nX4 / 256, 256>>>(attn, Ahi, Alo, nX4);
    split_kernel<<<nW4 / 256, 256>>>(wo, Whi, Wlo, nW4);
    gemm_tc<<<gg, 256, G_TOTAL>>>(Ahi, Alo, Whi, Wlo, out, ROWS, DD, DD);
}

// round 12
// speedup vs baseline: 2.0237x; 1.0732x over previous
#include <cuda_runtime.h>
#include <cuda_bf16.h>
#include <cuda_fp16.h>
#include <cstdint>
#include <math.h>

#define TT  4096     // T
#define DD  1024     // D
#define HH  16
#define DH  64
#define BHN 32       // B*H
#define ROWS 8192    // B*T
#define FD  512      // 2m
#define MR2 (ROWS * HH)   // 131072 head-rows

// ---------------- scratch (device globals; no runtime allocation) ----------------
__device__ float g_Q[ROWS * DD];
__device__ float g_K[ROWS * DD];
__device__ float g_V[ROWS * DD];
__device__ float g_attn[ROWS * DD];
__device__ float g_part[512 * 8192 + 512 * 128];     // KV partials + ksum partials
__device__ float g_scale[MR2];
__device__ float g_amax[1];
__device__ __half g_At16[ROWS * DD];
__device__ __half g_Wh[DD * DD];
__device__ __nv_bfloat16 g_Ahi[ROWS * DD];
__device__ __nv_bfloat16 g_Alo[ROWS * DD];
__device__ __nv_bfloat16 g_Whi[DD * DD];
__device__ __nv_bfloat16 g_Wlo[DD * DD];
__device__ __nv_bfloat16 g_Qfh[BHN * TT * FD];
__device__ __nv_bfloat16 g_Qfl[BHN * TT * FD];
__device__ __nv_bfloat16 g_Kfh[BHN * TT * FD];
__device__ __nv_bfloat16 g_Kfl[BHN * TT * FD];
__device__ __nv_bfloat16 g_Vhi[ROWS * DD];
__device__ __nv_bfloat16 g_Vlo[ROWS * DD];
__device__ __nv_bfloat16 g_KVThi[BHN * 72 * FD];
__device__ __nv_bfloat16 g_KVTlo[BHN * 72 * FD];

#define KS_OFF (512 * 8192)

// =================== base-target PTX helpers (no tcgen05!) =======================
__device__ __forceinline__ uint32_t smem_u32(const void* p) {
    uint32_t a;
    asm("{ .reg .u64 t; cvta.to.shared.u64 t, %1; cvt.u32.u64 %0, t; }" : "=r"(a) : "l"(p));
    return a;
}
#define CP_ASYNC16(saddr, gptr) \
    asm volatile("cp.async.cg.shared.global [%0], [%1], 16;" :: "r"(saddr), "l"(gptr))
#define CP_ASYNC_COMMIT() asm volatile("cp.async.commit_group;" ::: "memory")
#define CP_ASYNC_WAIT1()  asm volatile("cp.async.wait_group 1;" ::: "memory")
#define CP_ASYNC_WAIT0()  asm volatile("cp.async.wait_group 0;" ::: "memory")
#define LDMATRIX_X4(r, addr) \
    asm volatile("ldmatrix.sync.aligned.m8n8.x4.shared.b16 {%0,%1,%2,%3}, [%4];" \
        : "=r"((r)[0]), "=r"((r)[1]), "=r"((r)[2]), "=r"((r)[3]) : "r"(addr))
#define LDMATRIX_X2(r, addr) \
    asm volatile("ldmatrix.sync.aligned.m8n8.x2.shared.b16 {%0,%1}, [%2];" \
        : "=r"((r)[0]), "=r"((r)[1]) : "r"(addr))
#define LDMATRIX_X4_TRANS(r, addr) \
    asm volatile("ldmatrix.sync.aligned.m8n8.x4.trans.shared.b16 {%0,%1,%2,%3}, [%4];" \
        : "=r"((r)[0]), "=r"((r)[1]), "=r"((r)[2]), "=r"((r)[3]) : "r"(addr))
#define LDMATRIX_X2_TRANS(r, addr) \
    asm volatile("ldmatrix.sync.aligned.m8n8.x2.trans.shared.b16 {%0,%1}, [%2];" \
        : "=r"((r)[0]), "=r"((r)[1]) : "r"(addr))
#define MMA16816(c, a, b) \
    asm volatile("mma.sync.aligned.m16n8k16.row.col.f32.bf16.bf16.f32 " \
        "{%0,%1,%2,%3}, {%4,%5,%6,%7}, {%8,%9}, {%0,%1,%2,%3};" \
        : "+f"((c)[0]), "+f"((c)[1]), "+f"((c)[2]), "+f"((c)[3]) \
        : "r"((a)[0]), "r"((a)[1]), "r"((a)[2]), "r"((a)[3]), "r"((b)[0]), "r"((b)[1]))
#define MMAF16(c, a, b) \
    asm volatile("mma.sync.aligned.m16n8k16.row.col.f32.f16.f16.f32 " \
        "{%0,%1,%2,%3}, {%4,%5,%6,%7}, {%8,%9}, {%0,%1,%2,%3};" \
        : "+f"((c)[0]), "+f"((c)[1]), "+f"((c)[2]), "+f"((c)[3]) \
        : "r"((a)[0]), "r"((a)[1]), "r"((a)[2]), "r"((a)[3]), "r"((b)[0]), "r"((b)[1]))
#define SWZ128(off) ((off) ^ (((off) >> 3) & 0x70))

// =================== HMMA bf16x3 split GEMM (precision-critical projections) =====
#define G_STAGE 32768
#define G_AHI 0
#define G_ALO 8192
#define G_BHI 16384
#define G_BLO 24576
#define G_TOTAL (2 * G_STAGE)

__global__ __launch_bounds__(256)
void gemm_tc(const __nv_bfloat16* __restrict__ Ahi, const __nv_bfloat16* __restrict__ Alo,
             const __nv_bfloat16* __restrict__ Bhi, const __nv_bfloat16* __restrict__ Blo,
             float* __restrict__ C, int M, int N, int K) {
    extern __shared__ char smem[];
    const uint32_t sbase = smem_u32(smem);
    const int tid = threadIdx.x;
    const int wid = tid >> 5, lane = tid & 31;
    const int warpM = (wid >> 2) * 64;
    const int warpN = (wid & 3) * 32;
    const int brow = blockIdx.y * 128;
    const int bcol = blockIdx.x * 128;

    float acc[4][4][4];
#pragma unroll
    for (int i = 0; i < 4; i++)
#pragma unroll
        for (int j = 0; j < 4; j++)
#pragma unroll
            for (int r = 0; r < 4; r++) acc[i][j][r] = 0.f;

    const int r0 = tid >> 2, c0 = tid & 3;
    const int r1 = (tid + 256) >> 2, c1 = c0;
    const uint32_t so0 = (uint32_t)(r0 * 64 + ((c0 ^ ((r0 >> 1) & 3)) * 16));
    const uint32_t so1 = (uint32_t)(r1 * 64 + ((c1 ^ ((r1 >> 1) & 3)) * 16));

    const int nchunk = K >> 5;

#define ISSUE_CHUNK(ch, stg) do { \
    const int _k0 = (ch) << 5; \
    const uint32_t _st = sbase + (stg) * G_STAGE; \
    const size_t _ga0 = (size_t)(brow + r0) * K + _k0 + c0 * 8; \
    const size_t _ga1 = (size_t)(brow + r1) * K + _k0 + c1 * 8; \
    const size_t _gb0 = (size_t)(bcol + r0) * K + _k0 + c0 * 8; \
    const size_t _gb1 = (size_t)(bcol + r1) * K + _k0 + c1 * 8; \
    CP_ASYNC16(_st + G_AHI + so0, Ahi + _ga0); \
    CP_ASYNC16(_st + G_AHI + so1, Ahi + _ga1); \
    CP_ASYNC16(_st + G_ALO + so0, Alo + _ga0); \
    CP_ASYNC16(_st + G_ALO + so1, Alo + _ga1); \
    CP_ASYNC16(_st + G_BHI + so0, Bhi + _gb0); \
    CP_ASYNC16(_st + G_BHI + so1, Bhi + _gb1); \
    CP_ASYNC16(_st + G_BLO + so0, Blo + _gb0); \
    CP_ASYNC16(_st + G_BLO + so1, Blo + _gb1); \
    CP_ASYNC_COMMIT(); \
} while (0)

    ISSUE_CHUNK(0, 0);

    for (int ch = 0; ch < nchunk; ch++) {
        const int s = ch & 1;
        if (ch + 1 < nchunk) { ISSUE_CHUNK(ch + 1, s ^ 1); CP_ASYNC_WAIT1(); }
        else                 { CP_ASYNC_WAIT0(); }
        __syncthreads();

        const uint32_t st = sbase + s * G_STAGE;
#pragma unroll
        for (int kk = 0; kk < 2; kk++) {
            const int cb = kk * 2;
            uint32_t bh[4][2], bl[4][2];
#pragma unroll
            for (int ni = 0; ni < 4; ni++) {
                const int n = warpN + ni * 8 + (lane & 7);
                const int chk = cb + ((lane >> 3) & 1);
                const uint32_t ad = st + G_BHI + (uint32_t)(n * 64 + ((chk ^ ((n >> 1) & 3)) * 16));
                LDMATRIX_X2(bh[ni], ad);
                LDMATRIX_X2(bl[ni], ad + 8192);
            }
            uint32_t af[4][4];
#pragma unroll
            for (int mi = 0; mi < 4; mi++) {
                const int m = warpM + mi * 16 + (lane & 15);
                const int chk = cb + (lane >> 4);
                const uint32_t ad = st + G_AHI + (uint32_t)(m * 64 + ((chk ^ ((m >> 1) & 3)) * 16));
                LDMATRIX_X4(af[mi], ad);
            }
#pragma unroll
            for (int mi = 0; mi < 4; mi++)
#pragma unroll
                for (int ni = 0; ni < 4; ni++) MMA16816(acc[mi][ni], af[mi], bh[ni]);
#pragma unroll
            for (int mi = 0; mi < 4; mi++)
#pragma unroll
                for (int ni = 0; ni < 4; ni++) MMA16816(acc[mi][ni], af[mi], bl[ni]);
#pragma unroll
            for (int mi = 0; mi < 4; mi++) {
                const int m = warpM + mi * 16 + (lane & 15);
                const int chk = cb + (lane >> 4);
                const uint32_t ad = st + G_ALO + (uint32_t)(m * 64 + ((chk ^ ((m >> 1) & 3)) * 16));
                LDMATRIX_X4(af[mi], ad);
            }
#pragma unroll
            for (int mi = 0; mi < 4; mi++)
#pragma unroll
                for (int ni = 0; ni < 4; ni++) MMA16816(acc[mi][ni], af[mi], bh[ni]);
        }
        __syncthreads();
    }
#undef ISSUE_CHUNK

#pragma unroll
    for (int mi = 0; mi < 4; mi++) {
        const int row = brow + warpM + mi * 16 + (lane >> 2);
#pragma unroll
        for (int ni = 0; ni < 4; ni++) {
            const int col = bcol + warpN + ni * 8 + (lane & 3) * 2;
            *(float2*)(C + (size_t)row * N + col)       = make_float2(acc[mi][ni][0], acc[mi][ni][1]);
            *(float2*)(C + (size_t)(row + 8) * N + col) = make_float2(acc[mi][ni][2], acc[mi][ni][3]);
        }
    }
}

// =================== single-pass fp16 HMMA GEMM (wo projection, scaled) ==========
// C[M,N] = (A[M,K] * B[N,K]^T) * invs  where invs is derived from *amax.
// 3-stage cp.async, single __syncthreads per chunk.
#define F_STAGE 16384
#define F_TOTAL (3 * F_STAGE)

__global__ __launch_bounds__(256)
void gemm_f16(const __half* __restrict__ A, const __half* __restrict__ B,
              float* __restrict__ C, const float* __restrict__ amax,
              int M, int N, int K) {
    extern __shared__ char smem[];
    const uint32_t sbase = smem_u32(smem);
    const int tid = threadIdx.x;
    const int wid = tid >> 5, lane = tid & 31;
    const int warpM = (wid >> 2) * 64;
    const int warpN = (wid & 3) * 32;
    const int brow = blockIdx.y * 128;
    const int bcol = blockIdx.x * 128;

    float acc[4][4][4];
#pragma unroll
    for (int i = 0; i < 4; i++)
#pragma unroll
        for (int j = 0; j < 4; j++)
#pragma unroll
            for (int r = 0; r < 4; r++) acc[i][j][r] = 0.f;

    const int r0 = tid >> 2, c0 = tid & 3;
    const int r1 = r0 + 64;
    const uint32_t so0 = (uint32_t)(r0 * 64 + ((c0 ^ ((r0 >> 1) & 3)) * 16));
    const uint32_t so1 = (uint32_t)(r1 * 64 + ((c0 ^ ((r1 >> 1) & 3)) * 16));

    const int nchunk = K >> 5;

#define F16_ISSUE(ch) do { \
    const uint32_t _st = sbase + ((ch) % 3) * F_STAGE; \
    const int _k0 = (ch) << 5; \
    CP_ASYNC16(_st + so0, A + (size_t)(brow + r0) * K + _k0 + c0 * 8); \
    CP_ASYNC16(_st + so1, A + (size_t)(brow + r1) * K + _k0 + c0 * 8); \
    CP_ASYNC16(_st + 8192 + so0, B + (size_t)(bcol + r0) * K + _k0 + c0 * 8); \
    CP_ASYNC16(_st + 8192 + so1, B + (size_t)(bcol + r1) * K + _k0 + c0 * 8); \
    CP_ASYNC_COMMIT(); \
} while (0)

    F16_ISSUE(0);
    F16_ISSUE(1);

    for (int ch = 0; ch < nchunk; ch++) {
        if (ch + 1 < nchunk) CP_ASYNC_WAIT1(); else CP_ASYNC_WAIT0();
        __syncthreads();
        if (ch + 2 < nchunk) F16_ISSUE(ch + 2);

        const uint32_t st = sbase + (ch % 3) * F_STAGE;
#pragma unroll
        for (int kk = 0; kk < 2; kk++) {
            const int cb = kk * 2;
            uint32_t bf[4][2];
#pragma unroll
            for (int ni = 0; ni < 4; ni++) {
                const int n = warpN + ni * 8 + (lane & 7);
                const int chk = cb + ((lane >> 3) & 1);
                const uint32_t ad = st + 8192 + (uint32_t)(n * 64 + ((chk ^ ((n >> 1) & 3)) * 16));
                LDMATRIX_X2(bf[ni], ad);
            }
            uint32_t af[4][4];
#pragma unroll
            for (int mi = 0; mi < 4; mi++) {
                const int m = warpM + mi * 16 + (lane & 15);
                const int chk = cb + (lane >> 4);
                const uint32_t ad = st + (uint32_t)(m * 64 + ((chk ^ ((m >> 1) & 3)) * 16));
                LDMATRIX_X4(af[mi], ad);
            }
#pragma unroll
            for (int mi = 0; mi < 4; mi++)
#pragma unroll
                for (int ni = 0; ni < 4; ni++) MMAF16(acc[mi][ni], af[mi], bf[ni]);
        }
    }
#undef F16_ISSUE

    // inverse of the scale applied to A (attn): s = 2^(14 - e), invs = 2^(e - 14)
    float am = fmaxf(*amax, 1e-30f);
    int e;
    frexpf(am, &e);
    const float invs = ldexpf(1.f, e - 14);

#pragma unroll
    for (int mi = 0; mi < 4; mi++) {
        const int row = brow + warpM + mi * 16 + (lane >> 2);
#pragma unroll
        for (int ni = 0; ni < 4; ni++) {
            const int col = bcol + warpN + ni * 8 + (lane & 3) * 2;
            *(float2*)(C + (size_t)row * N + col) =
                make_float2(acc[mi][ni][0] * invs, acc[mi][ni][1] * invs);
            *(float2*)(C + (size_t)(row + 8) * N + col) =
                make_float2(acc[mi][ni][2] * invs, acc[mi][ni][3] * invs);
        }
    }
}

// ---------------- fp32 -> fp16 convert (weights) ---------------------------------
__global__ __launch_bounds__(256) void conv16(const float* __restrict__ src,
                                              __half* __restrict__ dst, int n4) {
    int i = blockIdx.x * blockDim.x + threadIdx.x;
    if (i >= n4) return;
    float4 v = ((const float4*)src)[i];
    __half2* d = (__half2*)dst;
    d[2 * i + 0] = __floats2half2_rn(v.x, v.y);
    d[2 * i + 1] = __floats2half2_rn(v.z, v.w);
}

// ---------------- zero amax ------------------------------------------------------
__global__ void zero_amax(float* a) { a[0] = 0.f; }

// ---------------- attn fp32 -> scaled fp16 ---------------------------------------
__global__ __launch_bounds__(256) void attn_to_f16(const float* __restrict__ src,
                                                   __half* __restrict__ dst,
                                                   const float* __restrict__ amax, int n4) {
    int i = blockIdx.x * blockDim.x + threadIdx.x;
    if (i >= n4) return;
    float am = fmaxf(*amax, 1e-30f);
    int e;
    frexpf(am, &e);
    const float s = ldexpf(1.f, 14 - e);
    float4 v = ((const float4*)src)[i];
    __half2* d = (__half2*)dst;
    d[2 * i + 0] = __floats2half2_rn(v.x * s, v.y * s);
    d[2 * i + 1] = __floats2half2_rn(v.z * s, v.w * s);
}

// ---------------- fp32 -> bf16 hi/lo split (vectorized) --------------------------
__global__ __launch_bounds__(256) void split_kernel(const float* __restrict__ src,
                                                    __nv_bfloat16* __restrict__ hi,
                                                    __nv_bfloat16* __restrict__ lo,
                                                    int n4) {
    int i = blockIdx.x * blockDim.x + threadIdx.x;
    if (i >= n4) return;
    float4 v = ((const float4*)src)[i];
    __nv_bfloat16 hx = __float2bfloat16(v.x);
    __nv_bfloat16 hy = __float2bfloat16(v.y);
    __nv_bfloat16 hz = __float2bfloat16(v.z);
    __nv_bfloat16 hw = __float2bfloat16(v.w);
    __nv_bfloat162* hp = (__nv_bfloat162*)hi;
    __nv_bfloat162* lp = (__nv_bfloat162*)lo;
    hp[2 * i + 0] = __nv_bfloat162{hx, hy};
    hp[2 * i + 1] = __nv_bfloat162{hz, hw};
    lp[2 * i + 0] = __nv_bfloat162{__float2bfloat16(v.x - __bfloat162float(hx)),
                                   __float2bfloat16(v.y - __bfloat162float(hy))};
    lp[2 * i + 1] = __nv_bfloat162{__float2bfloat16(v.z - __bfloat162float(hz)),
                                   __float2bfloat16(v.w - __bfloat162float(hw))};
}

// ---------------- split + per-head-row norm/scale --------------------------------
__global__ __launch_bounds__(256) void split_norm(const float* __restrict__ src,
                                                  __nv_bfloat16* __restrict__ hi,
                                                  __nv_bfloat16* __restrict__ lo,
                                                  float* __restrict__ scale) {
    const int gidx = blockIdx.x * blockDim.x + threadIdx.x;
    float4 v = ((const float4*)src)[gidx];
    float ns = v.x * v.x + v.y * v.y + v.z * v.z + v.w * v.w;
#pragma unroll
    for (int m = 8; m >= 1; m >>= 1) ns += __shfl_xor_sync(0xffffffffu, ns, m);
    __nv_bfloat16 hx = __float2bfloat16(v.x);
    __nv_bfloat16 hy = __float2bfloat16(v.y);
    __nv_bfloat16 hz = __float2bfloat16(v.z);
    __nv_bfloat16 hw = __float2bfloat16(v.w);
    __nv_bfloat162* hp = (__nv_bfloat162*)hi;
    __nv_bfloat162* lp = (__nv_bfloat162*)lo;
    hp[2 * gidx + 0] = __nv_bfloat162{hx, hy};
    hp[2 * gidx + 1] = __nv_bfloat162{hz, hw};
    lp[2 * gidx + 0] = __nv_bfloat162{__float2bfloat16(v.x - __bfloat162float(hx)),
                                      __float2bfloat16(v.y - __bfloat162float(hy))};
    lp[2 * gidx + 1] = __nv_bfloat162{__float2bfloat16(v.z - __bfloat162float(hz)),
                                      __float2bfloat16(v.w - __bfloat162float(hw))};
    if ((gidx & 15) == 0)
        scale[gidx >> 4] = expf(-0.5f * ns) * 0.0625f;
}

// ---------------- phi GEMM + staged bf16 hi/lo output ----------------------------
#define P_AHI 0
#define P_ALO 16384
#define P_BHI 32768
#define P_BLO 49152
#define P_SC  65536
#define P_TOTAL (P_SC + 512)

__global__ __launch_bounds__(256)
void phi_gemm(const __nv_bfloat16* __restrict__ Ahi, const __nv_bfloat16* __restrict__ Alo,
              const __nv_bfloat16* __restrict__ Bhi, const __nv_bfloat16* __restrict__ Blo,
              const float* __restrict__ scale,
              __nv_bfloat16* __restrict__ outH, __nv_bfloat16* __restrict__ outL) {
    extern __shared__ char smem[];
    const uint32_t sbase = smem_u32(smem);
    float* scale_s = (float*)(smem + P_SC);
    const int tid = threadIdx.x;
    const int wid = tid >> 5, lane = tid & 31;
    const int warpM = (wid >> 2) * 64;
    const int warpN = (wid & 3) * 32;
    const int brow = blockIdx.y * 128;
    const int bcol = blockIdx.x * 128;

    for (int u = tid; u < 1024; u += 256) {
        const int row = u >> 3, c = u & 7;
        const uint32_t soff = SWZ128((uint32_t)(row * 128 + c * 16));
        const size_t ga = (size_t)(brow + row) * 64 + c * 8;
        const size_t gb = (size_t)(bcol + row) * 64 + c * 8;
        CP_ASYNC16(sbase + P_AHI + soff, Ahi + ga);
        CP_ASYNC16(sbase + P_ALO + soff, Alo + ga);
        CP_ASYNC16(sbase + P_BHI + soff, Bhi + gb);
        CP_ASYNC16(sbase + P_BLO + soff, Blo + gb);
    }
    CP_ASYNC_COMMIT();
    if (tid < 128) scale_s[tid] = scale[brow + tid];
    CP_ASYNC_WAIT0();
    __syncthreads();

    float acc[4][4][4];
#pragma unroll
    for (int i = 0; i < 4; i++)
#pragma unroll
        for (int j = 0; j < 4; j++)
#pragma unroll
            for (int r = 0; r < 4; r++) acc[i][j][r] = 0.f;

#pragma unroll
    for (int kk = 0; kk < 4; kk++) {
        uint32_t bh[4][2], bl[4][2];
#pragma unroll
        for (int ni = 0; ni < 4; ni++) {
            const int n = warpN + ni * 8 + (lane & 7);
            const uint32_t bc = (uint32_t)(kk * 32 + ((lane >> 3) & 1) * 16);
            const uint32_t ad = sbase + P_BHI + SWZ128((uint32_t)(n * 128) + bc);
            LDMATRIX_X2(bh[ni], ad);
            LDMATRIX_X2(bl[ni], ad + 16384);
        }
        uint32_t af[4][4];
#pragma unroll
        for (int mi = 0; mi < 4; mi++) {
            const int m = warpM + mi * 16 + (lane & 15);
            const uint32_t bc = (uint32_t)(kk * 32 + (lane >> 4) * 16);
            const uint32_t ad = sbase + P_AHI + SWZ128((uint32_t)(m * 128) + bc);
            LDMATRIX_X4(af[mi], ad);
        }
#pragma unroll
        for (int mi = 0; mi < 4; mi++)
#pragma unroll
            for (int ni = 0; ni < 4; ni++) MMA16816(acc[mi][ni], af[mi], bh[ni]);
#pragma unroll
        for (int mi = 0; mi < 4; mi++)
#pragma unroll
            for (int ni = 0; ni < 4; ni++) MMA16816(acc[mi][ni], af[mi], bl[ni]);
#pragma unroll
        for (int mi = 0; mi < 4; mi++) {
            const int m = warpM + mi * 16 + (lane & 15);
            const uint32_t bc = (uint32_t)(kk * 32 + (lane >> 4) * 16);
            const uint32_t ad = sbase + P_ALO + SWZ128((uint32_t)(m * 128) + bc);
            LDMATRIX_X4(af[mi], ad);
        }
#pragma unroll
        for (int mi = 0; mi < 4; mi++)
#pragma unroll
            for (int ni = 0; ni < 4; ni++) MMA16816(acc[mi][ni], af[mi], bh[ni]);
    }

    // ---- staged epilogue: 4 passes (cos/sin x hi/lo), coalesced writes ----
    const int orow = tid >> 1, ohalf = tid & 1;
    const int grow = brow + orow;
    const int b = grow >> 16;
    const int rem = grow & 65535;
    const int t = rem >> 4;
    const int h = rem & 15;
    const size_t obase = ((size_t)(((b << 4) + h)) * TT + t) * FD;

#pragma unroll
    for (int pass = 0; pass < 4; pass++) {
        const bool iscos = (pass < 2);
        const bool ishi  = ((pass & 1) == 0);
        __syncthreads();
#pragma unroll
        for (int mi = 0; mi < 4; mi++) {
#pragma unroll
            for (int rr = 0; rr < 2; rr++) {
                const int row = warpM + mi * 16 + (lane >> 2) + rr * 8;
                const float sc = scale_s[row];
#pragma unroll
                for (int ni = 0; ni < 4; ni++) {
                    const int col = warpN + ni * 8 + (lane & 3) * 2;
                    float v0 = acc[mi][ni][rr * 2 + 0];
                    float v1 = acc[mi][ni][rr * 2 + 1];
                    v0 = (iscos ? __cosf(v0) : __sinf(v0)) * sc;
                    v1 = (iscos ? __cosf(v1) : __sinf(v1)) * sc;
                    if (!ishi) {
                        v0 = v0 - __bfloat162float(__float2bfloat16(v0));
                        v1 = v1 - __bfloat162float(__float2bfloat16(v1));
                    }
                    __nv_bfloat162 pk{__float2bfloat16(v0), __float2bfloat16(v1)};
                    *(__nv_bfloat162*)(smem + (size_t)(row * 136 + col) * 2) = pk;
                }
            }
        }
        __syncthreads();
        const int colbase = (iscos ? bcol : bcol + 256);
        char* dp = (char*)((ishi ? outH : outL) + obase + colbase + ohalf * 64);
        const char* sp = smem + orow * 272 + ohalf * 128;
#pragma unroll
        for (int j = 0; j < 16; j++)
            *(uint2*)(dp + j * 8) = *(const uint2*)(sp + j * 8);
    }
}

// =================== kv HMMA: C[f,d] = sum_t Kf[t,f] V[t,d] (+ ksum) =============
#define KV_KHI 0
#define KV_KLO 8192
#define KV_VHI 16384
#define KV_VLO 20480
#define KV_STAGE 24576
#define KV_TOTAL (2 * KV_STAGE)

__global__ __launch_bounds__(256)
void kv_tc(const __nv_bfloat16* __restrict__ Kfh, const __nv_bfloat16* __restrict__ Kfl,
           const __nv_bfloat16* __restrict__ Vhi, const __nv_bfloat16* __restrict__ Vlo,
           float* __restrict__ part) {
    extern __shared__ char smem[];
    const uint32_t sbase = smem_u32(smem);
    const int tid = threadIdx.x, wid = tid >> 5, lane = tid & 31;
    const int bh = blockIdx.y, b = bh >> 4, h = bh & 15;
    const int ftile = blockIdx.x >> 2, tsplit = blockIdx.x & 3;
    const int warpM = wid * 16;
    const int fbase = ftile * 128;
    const size_t tb0 = (size_t)bh * TT + tsplit * 1024;
    const size_t vb0 = (size_t)b * TT + tsplit * 1024;

    float acc[8][4];
#pragma unroll
    for (int i = 0; i < 8; i++)
#pragma unroll
        for (int r = 0; r < 4; r++) acc[i][r] = 0.f;
    float ks = 0.f;

    const int tA0 = tid >> 4, cA0 = tid & 15;
    const int tA1 = (tid + 256) >> 4;
    const uint32_t sA0 = (uint32_t)(tA0 * 256 + ((cA0 ^ (tA0 & 7)) * 16));
    const uint32_t sA1 = (uint32_t)(tA1 * 256 + ((cA0 ^ (tA1 & 7)) * 16));
    const int tV = tid >> 3, cV = tid & 7;
    const uint32_t sV = (uint32_t)(tV * 128 + ((cV ^ (tV & 7)) * 16));

#define KV_ISSUE(ch, stg) do { \
    const uint32_t _st = sbase + (stg) * KV_STAGE; \
    const size_t _t0 = tb0 + (ch) * 32; \
    const size_t _v0 = vb0 + (ch) * 32; \
    CP_ASYNC16(_st + KV_KHI + sA0, Kfh + (_t0 + tA0) * FD + fbase + cA0 * 8); \
    CP_ASYNC16(_st + KV_KHI + sA1, Kfh + (_t0 + tA1) * FD + fbase + cA0 * 8); \
    CP_ASYNC16(_st + KV_KLO + sA0, Kfl + (_t0 + tA0) * FD + fbase + cA0 * 8); \
    CP_ASYNC16(_st + KV_KLO + sA1, Kfl + (_t0 + tA1) * FD + fbase + cA0 * 8); \
    CP_ASYNC16(_st + KV_VHI + sV, Vhi + (_v0 + tV) * DD + h * 64 + cV * 8); \
    CP_ASYNC16(_st + KV_VLO + sV, Vlo + (_v0 + tV) * DD + h * 64 + cV * 8); \
    CP_ASYNC_COMMIT(); \
} while (0)

    KV_ISSUE(0, 0);
    for (int ch = 0; ch < 32; ch++) {
        const int s = ch & 1;
        if (ch + 1 < 32) { KV_ISSUE(ch + 1, s ^ 1); CP_ASYNC_WAIT1(); }
        else             { CP_ASYNC_WAIT0(); }
        __syncthreads();
        const uint32_t st = sbase + s * KV_STAGE;
        {
            const int f = tid >> 1, th = tid & 1;
            const int cf = f >> 3, fo = (f & 7) * 2;
            const char* base = smem + s * KV_STAGE;
#pragma unroll
            for (int j = 0; j < 16; j++) {
                const int t = th * 16 + j;
                const uint32_t off = (uint32_t)(t * 256 + ((cf ^ (t & 7)) * 16) + fo);
                ks += __bfloat162float(*(const __nv_bfloat16*)(base + KV_KHI + off))
                    + __bfloat162float(*(const __nv_bfloat16*)(base + KV_KLO + off));
            }
        }
#pragma unroll
        for (int kt = 0; kt < 2; kt++) {
            const int k0 = kt * 16;
            const int ttA = k0 + (lane & 7) + ((lane >> 4) & 1) * 8;
            const int ccA = (warpM >> 3) + ((lane >> 3) & 1);
            const uint32_t aoff = (uint32_t)(ttA * 256 + ((ccA ^ (ttA & 7)) * 16));
            uint32_t ah[4], al[4];
            LDMATRIX_X4_TRANS(ah, st + KV_KHI + aoff);
            LDMATRIX_X4_TRANS(al, st + KV_KLO + aoff);
            const int ttB = k0 + (lane & 7) + ((lane >> 3) & 1) * 8;
            uint32_t bhf[8][2], blf[8][2];
#pragma unroll
            for (int ni = 0; ni < 8; ni++) {
                const uint32_t boff = (uint32_t)(ttB * 128 + ((ni ^ (ttB & 7)) * 16));
                LDMATRIX_X2_TRANS(bhf[ni], st + KV_VHI + boff);
                LDMATRIX_X2_TRANS(blf[ni], st + KV_VLO + boff);
            }
#pragma unroll
            for (int ni = 0; ni < 8; ni++) MMA16816(acc[ni], ah, bhf[ni]);
#pragma unroll
            for (int ni = 0; ni < 8; ni++) MMA16816(acc[ni], ah, blf[ni]);
#pragma unroll
            for (int ni = 0; ni < 8; ni++) MMA16816(acc[ni], al, bhf[ni]);
        }
        __syncthreads();
    }
#undef KV_ISSUE

    const int pidx = (bh * 4 + ftile) * 4 + tsplit;
    float* pb = part + (size_t)pidx * 8192;
    const int r = warpM + (lane >> 2);
    const int cb = (lane & 3) * 2;
#pragma unroll
    for (int ni = 0; ni < 8; ni++) {
        *(float2*)(pb + r * 64 + ni * 8 + cb)       = make_float2(acc[ni][0], acc[ni][1]);
        *(float2*)(pb + (r + 8) * 64 + ni * 8 + cb) = make_float2(acc[ni][2], acc[ni][3]);
    }
    const float ko = __shfl_xor_sync(0xffffffffu, ks, 1);
    if ((tid & 1) == 0)
        part[KS_OFF + pidx * 128 + (tid >> 1)] = ks + ko;
}

// ---------------- reduce partials -> bf16 split transposed KVT -------------------
__global__ __launch_bounds__(256) void kv_reduce2(const float* __restrict__ part,
                                                  __nv_bfloat16* __restrict__ KVThi,
                                                  __nv_bfloat16* __restrict__ KVTlo) {
    const int bh = blockIdx.x;
    const int tid = threadIdx.x;
    const size_t kb = (size_t)bh * 72 * FD;
    for (int idx = tid; idx < 64 * 512; idx += 256) {
        const int d = idx >> 9, f = idx & 511;
        const int ft = f >> 7, fl = f & 127;
        float v = 0.f;
#pragma unroll
        for (int ts = 0; ts < 4; ts++)
            v += part[(size_t)(((bh * 4 + ft) * 4 + ts)) * 8192 + fl * 64 + d];
        __nv_bfloat16 hi = __float2bfloat16(v);
        KVThi[kb + (size_t)d * FD + f] = hi;
        KVTlo[kb + (size_t)d * FD + f] = __float2bfloat16(v - __bfloat162float(hi));
    }
    for (int f = tid; f < 512; f += 256) {
        const int ft = f >> 7, fl = f & 127;
        float v = 0.f;
#pragma unroll
        for (int ts = 0; ts < 4; ts++)
            v += part[KS_OFF + ((bh * 4 + ft) * 4 + ts) * 128 + fl];
        __nv_bfloat16 hi = __float2bfloat16(v);
        KVThi[kb + (size_t)64 * FD + f] = hi;
        KVTlo[kb + (size_t)64 * FD + f] = __float2bfloat16(v - __bfloat162float(hi));
    }
    const __nv_bfloat16 z = __float2bfloat16(0.f);
    for (int idx = tid; idx < 7 * 512; idx += 256) {
        const int d = 65 + (idx >> 9), f = idx & 511;
        KVThi[kb + (size_t)d * FD + f] = z;
        KVTlo[kb + (size_t)d * FD + f] = z;
    }
}

// =================== qkv HMMA: out = (Qf x KVT^T)[:,0:64] / Z + amax -------------
#define QK_QHI 0
#define QK_QLO 8192
#define QK_BHI 16384
#define QK_BLO 20992
#define QK_STAGE 25600
#define QK_ZS (2 * QK_STAGE)
#define QK_TOTAL (QK_ZS + 512)

__global__ __launch_bounds__(256)
void qkv_tc(const __nv_bfloat16* __restrict__ Qfh, const __nv_bfloat16* __restrict__ Qfl,
            const __nv_bfloat16* __restrict__ KVThi, const __nv_bfloat16* __restrict__ KVTlo,
            float* __restrict__ attn, float* __restrict__ amax) {
    extern __shared__ char smem[];
    const uint32_t sbase = smem_u32(smem);
    const int tid = threadIdx.x, wid = tid >> 5, lane = tid & 31;
    const int bh = blockIdx.y, b = bh >> 4, h = bh & 15;
    const int tb = blockIdx.x;
    const int warpM = (wid >> 1) * 32;
    const int nodd = wid & 1;
    const int ntiles = 5 - nodd;
    const size_t qrow0 = (size_t)bh * TT + tb * 128;
    const size_t kvb = (size_t)bh * 72 * FD;

    float acc[2][5][4];
#pragma unroll
    for (int i = 0; i < 2; i++)
#pragma unroll
        for (int j = 0; j < 5; j++)
#pragma unroll
            for (int r = 0; r < 4; r++) acc[i][j][r] = 0.f;

    const int tQ0 = tid >> 2, cQ = tid & 3;
    const int tQ1 = (tid + 256) >> 2;
    const uint32_t sQ0 = (uint32_t)(tQ0 * 64 + ((cQ ^ ((tQ0 >> 1) & 3)) * 16));
    const uint32_t sQ1 = (uint32_t)(tQ1 * 64 + ((cQ ^ ((tQ1 >> 1) & 3)) * 16));
    const int dB0 = tid >> 2;
    const int dB1 = (tid + 256) >> 2;
    const uint32_t sB0 = (uint32_t)(dB0 * 64 + ((cQ ^ ((dB0 >> 1) & 3)) * 16));
    const uint32_t sB1 = (uint32_t)(dB1 * 64 + ((cQ ^ ((dB1 >> 1) & 3)) * 16));

#define QK_ISSUE(fc, stg) do { \
    const uint32_t _st = sbase + (stg) * QK_STAGE; \
    const int _f0 = (fc) * 32; \
    CP_ASYNC16(_st + QK_QHI + sQ0, Qfh + (qrow0 + tQ0) * FD + _f0 + cQ * 8); \
    CP_ASYNC16(_st + QK_QHI + sQ1, Qfh + (qrow0 + tQ1) * FD + _f0 + cQ * 8); \
    CP_ASYNC16(_st + QK_QLO + sQ0, Qfl + (qrow0 + tQ0) * FD + _f0 + cQ * 8); \
    CP_ASYNC16(_st + QK_QLO + sQ1, Qfl + (qrow0 + tQ1) * FD + _f0 + cQ * 8); \
    CP_ASYNC16(_st + QK_BHI + sB0, KVThi + kvb + (size_t)dB0 * FD + _f0 + cQ * 8); \
    CP_ASYNC16(_st + QK_BLO + sB0, KVTlo + kvb + (size_t)dB0 * FD + _f0 + cQ * 8); \
    if (tid < 32) { \
        CP_ASYNC16(_st + QK_BHI + sB1, KVThi + kvb + (size_t)dB1 * FD + _f0 + cQ * 8); \
        CP_ASYNC16(_st + QK_BLO + sB1, KVTlo + kvb + (size_t)dB1 * FD + _f0 + cQ * 8); \
    } \
    CP_ASYNC_COMMIT(); \
} while (0)

    QK_ISSUE(0, 0);
    for (int fc = 0; fc < 16; fc++) {
        const int s = fc & 1;
        if (fc + 1 < 16) { QK_ISSUE(fc + 1, s ^ 1); CP_ASYNC_WAIT1(); }
        else             { CP_ASYNC_WAIT0(); }
        __syncthreads();
        const uint32_t st = sbase + s * QK_STAGE;
#pragma unroll
        for (int kc = 0; kc < 2; kc++) {
            uint32_t ahf[2][4], alf[2][4];
#pragma unroll
            for (int mi = 0; mi < 2; mi++) {
                const int tt = warpM + mi * 16 + (lane & 7) + ((lane >> 3) & 1) * 8;
                const int cc = kc * 2 + ((lane >> 4) & 1);
                const uint32_t aoff = (uint32_t)(tt * 64 + ((cc ^ ((tt >> 1) & 3)) * 16));
                LDMATRIX_X4(ahf[mi], st + QK_QHI + aoff);
                LDMATRIX_X4(alf[mi], st + QK_QLO + aoff);
            }
            uint32_t bhf[5][2], blf[5][2];
#pragma unroll
            for (int ni = 0; ni < 5; ni++) {
                if (ni < ntiles) {
                    const int gt = ni + nodd * 5;
                    const int dd = gt * 8 + (lane & 7);
                    const int cc = kc * 2 + ((lane >> 3) & 1);
                    const uint32_t boff = (uint32_t)(dd * 64 + ((cc ^ ((dd >> 1) & 3)) * 16));
                    LDMATRIX_X2(bhf[ni], st + QK_BHI + boff);
                    LDMATRIX_X2(blf[ni], st + QK_BLO + boff);
                }
            }
#pragma unroll
            for (int mi = 0; mi < 2; mi++)
#pragma unroll
                for (int ni = 0; ni < 5; ni++)
                    if (ni < ntiles) MMA16816(acc[mi][ni], ahf[mi], bhf[ni]);
#pragma unroll
            for (int mi = 0; mi < 2; mi++)
#pragma unroll
                for (int ni = 0; ni < 5; ni++)
                    if (ni < ntiles) MMA16816(acc[mi][ni], ahf[mi], blf[ni]);
#pragma unroll
            for (int mi = 0; mi < 2; mi++)
#pragma unroll
                for (int ni = 0; ni < 5; ni++)
                    if (ni < ntiles) MMA16816(acc[mi][ni], alf[mi], bhf[ni]);
        }
        __syncthreads();
    }
#undef QK_ISSUE

    float* zsp = (float*)(smem + QK_ZS);
    if (nodd && (lane & 3) == 0) {
#pragma unroll
        for (int mi = 0; mi < 2; mi++) {
            const int r = warpM + mi * 16 + (lane >> 2);
            zsp[r] = acc[mi][3][0];
            zsp[r + 8] = acc[mi][3][2];
        }
    }
    __syncthreads();

    float lmax = 0.f;
    const size_t obase = ((size_t)b * TT + tb * 128) * DD + h * 64;
#pragma unroll
    for (int mi = 0; mi < 2; mi++) {
        const int r = warpM + mi * 16 + (lane >> 2);
        const float iz0 = 1.f / fmaxf(zsp[r], 1e-6f);
        const float iz1 = 1.f / fmaxf(zsp[r + 8], 1e-6f);
#pragma unroll
        for (int ni = 0; ni < 5; ni++) {
            if (ni < ntiles) {
                const int gt = ni + nodd * 5;
                if (gt == 8) continue;
                const int d = gt * 8 + (lane & 3) * 2;
                float o0 = acc[mi][ni][0] * iz0, o1 = acc[mi][ni][1] * iz0;
                float o2 = acc[mi][ni][2] * iz1, o3 = acc[mi][ni][3] * iz1;
                lmax = fmaxf(lmax, fmaxf(fmaxf(fabsf(o0), fabsf(o1)),
                                         fmaxf(fabsf(o2), fabsf(o3))));
                *(float2*)(attn + obase + (size_t)r * DD + d)       = make_float2(o0, o1);
                *(float2*)(attn + obase + (size_t)(r + 8) * DD + d) = make_float2(o2, o3);
            }
        }
    }
    atomicMax((int*)amax, __float_as_int(lmax));
}

// ---------------- launch ----------------------------------------------------------
extern "C" void kernel_launch(void* const* d_in, const int* in_sizes, int n_in,
                              void* d_out, int out_size) {
    (void)in_sizes; (void)n_in; (void)out_size;
    const float* x  = (const float*)d_in[0];
    const float* wq = (const float*)d_in[1];
    const float* wk = (const float*)d_in[2];
    const float* wv = (const float*)d_in[3];
    const float* wo = (const float*)d_in[4];
    const float* rf = (const float*)d_in[5];
    float* out = (float*)d_out;

    float *Q, *K, *V, *attn, *part, *scl, *amax;
    __half *At16, *Wh;
    __nv_bfloat16 *Ahi, *Alo, *Whi, *Wlo, *Qfh, *Qfl, *Kfh, *Kfl, *Vhi, *Vlo, *KVThi, *KVTlo;
    cudaGetSymbolAddress((void**)&Q,     g_Q);
    cudaGetSymbolAddress((void**)&K,     g_K);
    cudaGetSymbolAddress((void**)&V,     g_V);
    cudaGetSymbolAddress((void**)&attn,  g_attn);
    cudaGetSymbolAddress((void**)&part,  g_part);
    cudaGetSymbolAddress((void**)&scl,   g_scale);
    cudaGetSymbolAddress((void**)&amax,  g_amax);
    cudaGetSymbolAddress((void**)&At16,  g_At16);
    cudaGetSymbolAddress((void**)&Wh,    g_Wh);
    cudaGetSymbolAddress((void**)&Ahi,   g_Ahi);
    cudaGetSymbolAddress((void**)&Alo,   g_Alo);
    cudaGetSymbolAddress((void**)&Whi,   g_Whi);
    cudaGetSymbolAddress((void**)&Wlo,   g_Wlo);
    cudaGetSymbolAddress((void**)&Qfh,   g_Qfh);
    cudaGetSymbolAddress((void**)&Qfl,   g_Qfl);
    cudaGetSymbolAddress((void**)&Kfh,   g_Kfh);
    cudaGetSymbolAddress((void**)&Kfl,   g_Kfl);
    cudaGetSymbolAddress((void**)&Vhi,   g_Vhi);
    cudaGetSymbolAddress((void**)&Vlo,   g_Vlo);
    cudaGetSymbolAddress((void**)&KVThi, g_KVThi);
    cudaGetSymbolAddress((void**)&KVTlo, g_KVTlo);

    cudaFuncSetAttribute(gemm_tc,  cudaFuncAttributeMaxDynamicSharedMemorySize, G_TOTAL);
    cudaFuncSetAttribute(gemm_f16, cudaFuncAttributeMaxDynamicSharedMemorySize, F_TOTAL);
    cudaFuncSetAttribute(phi_gemm, cudaFuncAttributeMaxDynamicSharedMemorySize, P_TOTAL);
    cudaFuncSetAttribute(kv_tc,    cudaFuncAttributeMaxDynamicSharedMemorySize, KV_TOTAL);
    cudaFuncSetAttribute(qkv_tc,   cudaFuncAttributeMaxDynamicSharedMemorySize, QK_TOTAL);

    const int nX4 = ROWS * DD / 4;
    const int nW4 = DD * DD / 4;
    dim3 gg(DD / 128, ROWS / 128);

    // x split once, reused by the 3 bf16x3 projections
    split_kernel<<<nX4 / 256, 256>>>(x, Ahi, Alo, nX4);

    split_kernel<<<nW4 / 256, 256>>>(wq, Whi, Wlo, nW4);
    gemm_tc<<<gg, 256, G_TOTAL>>>(Ahi, Alo, Whi, Wlo, Q, ROWS, DD, DD);
    split_kernel<<<nW4 / 256, 256>>>(wk, Whi, Wlo, nW4);
    gemm_tc<<<gg, 256, G_TOTAL>>>(Ahi, Alo, Whi, Wlo, K, ROWS, DD, DD);
    split_kernel<<<nW4 / 256, 256>>>(wv, Whi, Wlo, nW4);
    gemm_tc<<<gg, 256, G_TOTAL>>>(Ahi, Alo, Whi, Wlo, V, ROWS, DD, DD);

    // V split for bf16x3 kv path
    split_kernel<<<nX4 / 256, 256>>>(V, Vhi, Vlo, nX4);

    // rf split (bf16 buffers)
    split_kernel<<<16, 256>>>(rf, Whi, Wlo, 256 * 64 / 4);

    // phi via bf16x3 HMMA with staged bf16 hi/lo output
    dim3 gp(2, MR2 / 128);
    split_norm<<<MR2 * 16 / 256, 256>>>(Q, Ahi, Alo, scl);
    phi_gemm<<<gp, 256, P_TOTAL>>>(Ahi, Alo, Whi, Wlo, scl, Qfh, Qfl);
    split_norm<<<MR2 * 16 / 256, 256>>>(K, Ahi, Alo, scl);
    phi_gemm<<<gp, 256, P_TOTAL>>>(Ahi, Alo, Whi, Wlo, scl, Kfh, Kfl);

    // kv + reduce + qkv (bf16x3 HMMA; qkv tracks attn absmax)
    zero_amax<<<1, 1>>>(amax);
    kv_tc<<<dim3(16, BHN), 256, KV_TOTAL>>>(Kfh, Kfl, Vhi, Vlo, part);
    kv_reduce2<<<BHN, 256>>>(part, KVThi, KVTlo);
    qkv_tc<<<dim3(TT / 128, BHN), 256, QK_TOTAL>>>(Qfh, Qfl, KVThi, KVTlo, attn, amax);

    // output projection: dynamically-scaled fp16 single-pass
    conv16<<<nW4 / 256, 256>>>(wo, Wh, nW4);
    attn_to_f16<<<nX4 / 256, 256>>>(attn, At16, amax, nX4);
    gemm_f16<<<gg, 256, F_TOTAL>>>(At16, Wh, out, amax, ROWS, DD, DD);
}

// round 14
// speedup vs baseline: 2.0679x; 1.0218x over previous
#include <cuda_runtime.h>
#include <cuda_bf16.h>
#include <cuda_fp16.h>
#include <cstdint>
#include <math.h>

#define TT  4096     // T
#define DD  1024     // D
#define HH  16
#define DH  64
#define BHN 32       // B*H
#define ROWS 8192    // B*T
#define FD  512      // 2m
#define MR2 (ROWS * HH)   // 131072 head-rows

// ---------------- scratch (device globals; no runtime allocation) ----------------
__device__ float g_Q[ROWS * DD];     // aliased as Qhi/Qlo bf16 splits
__device__ float g_K[ROWS * DD];     // aliased as Khi/Klo bf16 splits
__device__ float g_attn[ROWS * DD];  // first MR2 floats double as scaleK before qkv
__device__ float g_part[512 * 8192 + 512 * 128];     // KV partials + ksum partials
__device__ float g_scale[MR2];       // scaleQ
__device__ float g_amax[1];
__device__ __half g_At16[ROWS * DD];
__device__ __half g_Wh[DD * DD];
__device__ __nv_bfloat16 g_Ahi[ROWS * DD];
__device__ __nv_bfloat16 g_Alo[ROWS * DD];
__device__ __nv_bfloat16 g_Whi[DD * DD];
__device__ __nv_bfloat16 g_Wlo[DD * DD];
__device__ __nv_bfloat16 g_Qfh[BHN * TT * FD];
__device__ __nv_bfloat16 g_Qfl[BHN * TT * FD];
__device__ __nv_bfloat16 g_Kfh[BHN * TT * FD];
__device__ __nv_bfloat16 g_Kfl[BHN * TT * FD];
__device__ __nv_bfloat16 g_Vhi[ROWS * DD];
__device__ __nv_bfloat16 g_Vlo[ROWS * DD];
__device__ __nv_bfloat16 g_KVThi[BHN * 72 * FD];
__device__ __nv_bfloat16 g_KVTlo[BHN * 72 * FD];

#define KS_OFF (512 * 8192)

// =================== base-target PTX helpers (no tcgen05!) =======================
__device__ __forceinline__ uint32_t smem_u32(const void* p) {
    uint32_t a;
    asm("{ .reg .u64 t; cvta.to.shared.u64 t, %1; cvt.u32.u64 %0, t; }" : "=r"(a) : "l"(p));
    return a;
}
#define CP_ASYNC16(saddr, gptr) \
    asm volatile("cp.async.cg.shared.global [%0], [%1], 16;" :: "r"(saddr), "l"(gptr))
#define CP_ASYNC_COMMIT() asm volatile("cp.async.commit_group;" ::: "memory")
#define CP_ASYNC_WAIT1()  asm volatile("cp.async.wait_group 1;" ::: "memory")
#define CP_ASYNC_WAIT0()  asm volatile("cp.async.wait_group 0;" ::: "memory")
#define LDMATRIX_X4(r, addr) \
    asm volatile("ldmatrix.sync.aligned.m8n8.x4.shared.b16 {%0,%1,%2,%3}, [%4];" \
        : "=r"((r)[0]), "=r"((r)[1]), "=r"((r)[2]), "=r"((r)[3]) : "r"(addr))
#define LDMATRIX_X2(r, addr) \
    asm volatile("ldmatrix.sync.aligned.m8n8.x2.shared.b16 {%0,%1}, [%2];" \
        : "=r"((r)[0]), "=r"((r)[1]) : "r"(addr))
#define LDMATRIX_X4_TRANS(r, addr) \
    asm volatile("ldmatrix.sync.aligned.m8n8.x4.trans.shared.b16 {%0,%1,%2,%3}, [%4];" \
        : "=r"((r)[0]), "=r"((r)[1]), "=r"((r)[2]), "=r"((r)[3]) : "r"(addr))
#define LDMATRIX_X2_TRANS(r, addr) \
    asm volatile("ldmatrix.sync.aligned.m8n8.x2.trans.shared.b16 {%0,%1}, [%2];" \
        : "=r"((r)[0]), "=r"((r)[1]) : "r"(addr))
#define MMA16816(c, a, b) \
    asm volatile("mma.sync.aligned.m16n8k16.row.col.f32.bf16.bf16.f32 " \
        "{%0,%1,%2,%3}, {%4,%5,%6,%7}, {%8,%9}, {%0,%1,%2,%3};" \
        : "+f"((c)[0]), "+f"((c)[1]), "+f"((c)[2]), "+f"((c)[3]) \
        : "r"((a)[0]), "r"((a)[1]), "r"((a)[2]), "r"((a)[3]), "r"((b)[0]), "r"((b)[1]))
#define MMAF16(c, a, b) \
    asm volatile("mma.sync.aligned.m16n8k16.row.col.f32.f16.f16.f32 " \
        "{%0,%1,%2,%3}, {%4,%5,%6,%7}, {%8,%9}, {%0,%1,%2,%3};" \
        : "+f"((c)[0]), "+f"((c)[1]), "+f"((c)[2]), "+f"((c)[3]) \
        : "r"((a)[0]), "r"((a)[1]), "r"((a)[2]), "r"((a)[3]), "r"((b)[0]), "r"((b)[1]))
#define SWZ128(off) ((off) ^ (((off) >> 3) & 0x70))

// =================== HMMA bf16x3 split GEMM + fused split/norm epilogue ==========
// C = A*B^T in fp32 accum; epilogue writes bf16 hi/lo of C directly.
// DO_NORM: additionally computes per-head-row (64-col groups) squared norms and
// writes scale[row*(N/64)+head] = exp(-|c|^2/2)/16.
#define G_STAGE 32768
#define G_AHI 0
#define G_ALO 8192
#define G_BHI 16384
#define G_BLO 24576
#define G_TOTAL (2 * G_STAGE)

template <int DO_NORM>
__global__ __launch_bounds__(256)
void gemm_split(const __nv_bfloat16* __restrict__ Ahi, const __nv_bfloat16* __restrict__ Alo,
                const __nv_bfloat16* __restrict__ Bhi, const __nv_bfloat16* __restrict__ Blo,
                __nv_bfloat16* __restrict__ Chi, __nv_bfloat16* __restrict__ Clo,
                float* __restrict__ scale, int M, int N, int K) {
    extern __shared__ char smem[];
    const uint32_t sbase = smem_u32(smem);
    const int tid = threadIdx.x;
    const int wid = tid >> 5, lane = tid & 31;
    const int warpM = (wid >> 2) * 64;
    const int warpN = (wid & 3) * 32;
    const int brow = blockIdx.y * 128;
    const int bcol = blockIdx.x * 128;

    float acc[4][4][4];
#pragma unroll
    for (int i = 0; i < 4; i++)
#pragma unroll
        for (int j = 0; j < 4; j++)
#pragma unroll
            for (int r = 0; r < 4; r++) acc[i][j][r] = 0.f;

    const int r0 = tid >> 2, c0 = tid & 3;
    const int r1 = (tid + 256) >> 2, c1 = c0;
    const uint32_t so0 = (uint32_t)(r0 * 64 + ((c0 ^ ((r0 >> 1) & 3)) * 16));
    const uint32_t so1 = (uint32_t)(r1 * 64 + ((c1 ^ ((r1 >> 1) & 3)) * 16));

    const int nchunk = K >> 5;

#define ISSUE_CHUNK(ch, stg) do { \
    const int _k0 = (ch) << 5; \
    const uint32_t _st = sbase + (stg) * G_STAGE; \
    const size_t _ga0 = (size_t)(brow + r0) * K + _k0 + c0 * 8; \
    const size_t _ga1 = (size_t)(brow + r1) * K + _k0 + c1 * 8; \
    const size_t _gb0 = (size_t)(bcol + r0) * K + _k0 + c0 * 8; \
    const size_t _gb1 = (size_t)(bcol + r1) * K + _k0 + c1 * 8; \
    CP_ASYNC16(_st + G_AHI + so0, Ahi + _ga0); \
    CP_ASYNC16(_st + G_AHI + so1, Ahi + _ga1); \
    CP_ASYNC16(_st + G_ALO + so0, Alo + _ga0); \
    CP_ASYNC16(_st + G_ALO + so1, Alo + _ga1); \
    CP_ASYNC16(_st + G_BHI + so0, Bhi + _gb0); \
    CP_ASYNC16(_st + G_BHI + so1, Bhi + _gb1); \
    CP_ASYNC16(_st + G_BLO + so0, Blo + _gb0); \
    CP_ASYNC16(_st + G_BLO + so1, Blo + _gb1); \
    CP_ASYNC_COMMIT(); \
} while (0)

    ISSUE_CHUNK(0, 0);

    for (int ch = 0; ch < nchunk; ch++) {
        const int s = ch & 1;
        if (ch + 1 < nchunk) { ISSUE_CHUNK(ch + 1, s ^ 1); CP_ASYNC_WAIT1(); }
        else                 { CP_ASYNC_WAIT0(); }
        __syncthreads();

        const uint32_t st = sbase + s * G_STAGE;
#pragma unroll
        for (int kk = 0; kk < 2; kk++) {
            const int cb = kk * 2;
            uint32_t bh[4][2], bl[4][2];
#pragma unroll
            for (int ni = 0; ni < 4; ni++) {
                const int n = warpN + ni * 8 + (lane & 7);
                const int chk = cb + ((lane >> 3) & 1);
                const uint32_t ad = st + G_BHI + (uint32_t)(n * 64 + ((chk ^ ((n >> 1) & 3)) * 16));
                LDMATRIX_X2(bh[ni], ad);
                LDMATRIX_X2(bl[ni], ad + 8192);
            }
            uint32_t af[4][4];
#pragma unroll
            for (int mi = 0; mi < 4; mi++) {
                const int m = warpM + mi * 16 + (lane & 15);
                const int chk = cb + (lane >> 4);
                const uint32_t ad = st + G_AHI + (uint32_t)(m * 64 + ((chk ^ ((m >> 1) & 3)) * 16));
                LDMATRIX_X4(af[mi], ad);
            }
#pragma unroll
            for (int mi = 0; mi < 4; mi++)
#pragma unroll
                for (int ni = 0; ni < 4; ni++) MMA16816(acc[mi][ni], af[mi], bh[ni]);
#pragma unroll
            for (int mi = 0; mi < 4; mi++)
#pragma unroll
                for (int ni = 0; ni < 4; ni++) MMA16816(acc[mi][ni], af[mi], bl[ni]);
#pragma unroll
            for (int mi = 0; mi < 4; mi++) {
                const int m = warpM + mi * 16 + (lane & 15);
                const int chk = cb + (lane >> 4);
                const uint32_t ad = st + G_ALO + (uint32_t)(m * 64 + ((chk ^ ((m >> 1) & 3)) * 16));
                LDMATRIX_X4(af[mi], ad);
            }
#pragma unroll
            for (int mi = 0; mi < 4; mi++)
#pragma unroll
                for (int ni = 0; ni < 4; ni++) MMA16816(acc[mi][ni], af[mi], bh[ni]);
        }
        __syncthreads();
    }
#undef ISSUE_CHUNK

    // ---- fused epilogue: bf16 hi/lo split writes ----
#pragma unroll
    for (int mi = 0; mi < 4; mi++) {
        const int row = brow + warpM + mi * 16 + (lane >> 2);
#pragma unroll
        for (int ni = 0; ni < 4; ni++) {
            const int col = bcol + warpN + ni * 8 + (lane & 3) * 2;
#pragma unroll
            for (int rr = 0; rr < 2; rr++) {
                const size_t pos = (size_t)(row + rr * 8) * N + col;
                const float v0 = acc[mi][ni][rr * 2 + 0];
                const float v1 = acc[mi][ni][rr * 2 + 1];
                const __nv_bfloat16 h0 = __float2bfloat16(v0);
                const __nv_bfloat16 h1 = __float2bfloat16(v1);
                *(__nv_bfloat162*)(Chi + pos) = __nv_bfloat162{h0, h1};
                *(__nv_bfloat162*)(Clo + pos) =
                    __nv_bfloat162{__float2bfloat16(v0 - __bfloat162float(h0)),
                                   __float2bfloat16(v1 - __bfloat162float(h1))};
            }
        }
    }

    if (DO_NORM) {
        // per-thread squared sums over its 32-col (warpN) span, per row-half
        float ss[4][2];
#pragma unroll
        for (int mi = 0; mi < 4; mi++)
#pragma unroll
            for (int h = 0; h < 2; h++) {
                float s = 0.f;
#pragma unroll
                for (int ni = 0; ni < 4; ni++) {
                    const float a0 = acc[mi][ni][h * 2 + 0];
                    const float a1 = acc[mi][ni][h * 2 + 1];
                    s = fmaf(a0, a0, s);
                    s = fmaf(a1, a1, s);
                }
                ss[mi][h] = s;
            }
#pragma unroll
        for (int msk = 1; msk <= 2; msk <<= 1)
#pragma unroll
            for (int mi = 0; mi < 4; mi++)
#pragma unroll
                for (int h = 0; h < 2; h++)
                    ss[mi][h] += __shfl_xor_sync(0xffffffffu, ss[mi][h], msk);

        float* part = (float*)smem;   // [8 warps][128 tile rows] = 4 KB
        if ((lane & 3) == 0) {
#pragma unroll
            for (int mi = 0; mi < 4; mi++)
#pragma unroll
                for (int h = 0; h < 2; h++) {
                    const int r = warpM + mi * 16 + (lane >> 2) + h * 8;
                    part[wid * 128 + r] = ss[mi][h];
                }
        }
        __syncthreads();
        // 256 threads -> 128 rows x 2 tile-heads
        const int r = tid >> 1, hh = tid & 1;
        const int w0 = (r >> 6) * 4 + hh * 2;
        const float s = part[w0 * 128 + r] + part[(w0 + 1) * 128 + r];
        scale[(size_t)(brow + r) * (N >> 6) + (bcol >> 6) + hh] =
            expf(-0.5f * s) * 0.0625f;
    }
}

// =================== single-pass fp16 HMMA GEMM (wo projection, scaled) ==========
#define F_STAGE 16384
#define F_TOTAL (3 * F_STAGE)

__global__ __launch_bounds__(256)
void gemm_f16(const __half* __restrict__ A, const __half* __restrict__ B,
              float* __restrict__ C, const float* __restrict__ amax,
              int M, int N, int K) {
    extern __shared__ char smem[];
    const uint32_t sbase = smem_u32(smem);
    const int tid = threadIdx.x;
    const int wid = tid >> 5, lane = tid & 31;
    const int warpM = (wid >> 2) * 64;
    const int warpN = (wid & 3) * 32;
    const int brow = blockIdx.y * 128;
    const int bcol = blockIdx.x * 128;

    float acc[4][4][4];
#pragma unroll
    for (int i = 0; i < 4; i++)
#pragma unroll
        for (int j = 0; j < 4; j++)
#pragma unroll
            for (int r = 0; r < 4; r++) acc[i][j][r] = 0.f;

    const int r0 = tid >> 2, c0 = tid & 3;
    const int r1 = r0 + 64;
    const uint32_t so0 = (uint32_t)(r0 * 64 + ((c0 ^ ((r0 >> 1) & 3)) * 16));
    const uint32_t so1 = (uint32_t)(r1 * 64 + ((c0 ^ ((r1 >> 1) & 3)) * 16));

    const int nchunk = K >> 5;

#define F16_ISSUE(ch) do { \
    const uint32_t _st = sbase + ((ch) % 3) * F_STAGE; \
    const int _k0 = (ch) << 5; \
    CP_ASYNC16(_st + so0, A + (size_t)(brow + r0) * K + _k0 + c0 * 8); \
    CP_ASYNC16(_st + so1, A + (size_t)(brow + r1) * K + _k0 + c0 * 8); \
    CP_ASYNC16(_st + 8192 + so0, B + (size_t)(bcol + r0) * K + _k0 + c0 * 8); \
    CP_ASYNC16(_st + 8192 + so1, B + (size_t)(bcol + r1) * K + _k0 + c0 * 8); \
    CP_ASYNC_COMMIT(); \
} while (0)

    F16_ISSUE(0);
    F16_ISSUE(1);

    for (int ch = 0; ch < nchunk; ch++) {
        if (ch + 1 < nchunk) CP_ASYNC_WAIT1(); else CP_ASYNC_WAIT0();
        __syncthreads();
        if (ch + 2 < nchunk) F16_ISSUE(ch + 2);

        const uint32_t st = sbase + (ch % 3) * F_STAGE;
#pragma unroll
        for (int kk = 0; kk < 2; kk++) {
            const int cb = kk * 2;
            uint32_t bf[4][2];
#pragma unroll
            for (int ni = 0; ni < 4; ni++) {
                const int n = warpN + ni * 8 + (lane & 7);
                const int chk = cb + ((lane >> 3) & 1);
                const uint32_t ad = st + 8192 + (uint32_t)(n * 64 + ((chk ^ ((n >> 1) & 3)) * 16));
                LDMATRIX_X2(bf[ni], ad);
            }
            uint32_t af[4][4];
#pragma unroll
            for (int mi = 0; mi < 4; mi++) {
                const int m = warpM + mi * 16 + (lane & 15);
                const int chk = cb + (lane >> 4);
                const uint32_t ad = st + (uint32_t)(m * 64 + ((chk ^ ((m >> 1) & 3)) * 16));
                LDMATRIX_X4(af[mi], ad);
            }
#pragma unroll
            for (int mi = 0; mi < 4; mi++)
#pragma unroll
                for (int ni = 0; ni < 4; ni++) MMAF16(acc[mi][ni], af[mi], bf[ni]);
        }
    }
#undef F16_ISSUE

    float am = fmaxf(*amax, 1e-30f);
    int e;
    frexpf(am, &e);
    const float invs = ldexpf(1.f, e - 14);

#pragma unroll
    for (int mi = 0; mi < 4; mi++) {
        const int row = brow + warpM + mi * 16 + (lane >> 2);
#pragma unroll
        for (int ni = 0; ni < 4; ni++) {
            const int col = bcol + warpN + ni * 8 + (lane & 3) * 2;
            *(float2*)(C + (size_t)row * N + col) =
                make_float2(acc[mi][ni][0] * invs, acc[mi][ni][1] * invs);
            *(float2*)(C + (size_t)(row + 8) * N + col) =
                make_float2(acc[mi][ni][2] * invs, acc[mi][ni][3] * invs);
        }
    }
}

// ---------------- fp32 -> fp16 convert (weights) ---------------------------------
__global__ __launch_bounds__(256) void conv16(const float* __restrict__ src,
                                              __half* __restrict__ dst, int n4) {
    int i = blockIdx.x * blockDim.x + threadIdx.x;
    if (i >= n4) return;
    float4 v = ((const float4*)src)[i];
    __half2* d = (__half2*)dst;
    d[2 * i + 0] = __floats2half2_rn(v.x, v.y);
    d[2 * i + 1] = __floats2half2_rn(v.z, v.w);
}

// ---------------- zero amax ------------------------------------------------------
__global__ void zero_amax(float* a) { a[0] = 0.f; }

// ---------------- attn fp32 -> scaled fp16 ---------------------------------------
__global__ __launch_bounds__(256) void attn_to_f16(const float* __restrict__ src,
                                                   __half* __restrict__ dst,
                                                   const float* __restrict__ amax, int n4) {
    int i = blockIdx.x * blockDim.x + threadIdx.x;
    if (i >= n4) return;
    float am = fmaxf(*amax, 1e-30f);
    int e;
    frexpf(am, &e);
    const float s = ldexpf(1.f, 14 - e);
    float4 v = ((const float4*)src)[i];
    __half2* d = (__half2*)dst;
    d[2 * i + 0] = __floats2half2_rn(v.x * s, v.y * s);
    d[2 * i + 1] = __floats2half2_rn(v.z * s, v.w * s);
}

// ---------------- fp32 -> bf16 hi/lo split (vectorized) --------------------------
__global__ __launch_bounds__(256) void split_kernel(const float* __restrict__ src,
                                                    __nv_bfloat16* __restrict__ hi,
                                                    __nv_bfloat16* __restrict__ lo,
                                                    int n4) {
    int i = blockIdx.x * blockDim.x + threadIdx.x;
    if (i >= n4) return;
    float4 v = ((const float4*)src)[i];
    __nv_bfloat16 hx = __float2bfloat16(v.x);
    __nv_bfloat16 hy = __float2bfloat16(v.y);
    __nv_bfloat16 hz = __float2bfloat16(v.z);
    __nv_bfloat16 hw = __float2bfloat16(v.w);
    __nv_bfloat162* hp = (__nv_bfloat162*)hi;
    __nv_bfloat162* lp = (__nv_bfloat162*)lo;
    hp[2 * i + 0] = __nv_bfloat162{hx, hy};
    hp[2 * i + 1] = __nv_bfloat162{hz, hw};
    lp[2 * i + 0] = __nv_bfloat162{__float2bfloat16(v.x - __bfloat162float(hx)),
                                   __float2bfloat16(v.y - __bfloat162float(hy))};
    lp[2 * i + 1] = __nv_bfloat162{__float2bfloat16(v.z - __bfloat162float(hz)),
                                   __float2bfloat16(v.w - __bfloat162float(hw))};
}

// ---------------- phi GEMM + staged bf16 hi/lo output ----------------------------
#define P_AHI 0
#define P_ALO 16384
#define P_BHI 32768
#define P_BLO 49152
#define P_SC  65536
#define P_TOTAL (P_SC + 512)

__global__ __launch_bounds__(256)
void phi_gemm(const __nv_bfloat16* __restrict__ Ahi, const __nv_bfloat16* __restrict__ Alo,
              const __nv_bfloat16* __restrict__ Bhi, const __nv_bfloat16* __restrict__ Blo,
              const float* __restrict__ scale,
              __nv_bfloat16* __restrict__ outH, __nv_bfloat16* __restrict__ outL) {
    extern __shared__ char smem[];
    const uint32_t sbase = smem_u32(smem);
    float* scale_s = (float*)(smem + P_SC);
    const int tid = threadIdx.x;
    const int wid = tid >> 5, lane = tid & 31;
    const int warpM = (wid >> 2) * 64;
    const int warpN = (wid & 3) * 32;
    const int brow = blockIdx.y * 128;
    const int bcol = blockIdx.x * 128;

    for (int u = tid; u < 1024; u += 256) {
        const int row = u >> 3, c = u & 7;
        const uint32_t soff = SWZ128((uint32_t)(row * 128 + c * 16));
        const size_t ga = (size_t)(brow + row) * 64 + c * 8;
        const size_t gb = (size_t)(bcol + row) * 64 + c * 8;
        CP_ASYNC16(sbase + P_AHI + soff, Ahi + ga);
        CP_ASYNC16(sbase + P_ALO + soff, Alo + ga);
        CP_ASYNC16(sbase + P_BHI + soff, Bhi + gb);
        CP_ASYNC16(sbase + P_BLO + soff, Blo + gb);
    }
    CP_ASYNC_COMMIT();
    if (tid < 128) scale_s[tid] = scale[brow + tid];
    CP_ASYNC_WAIT0();
    __syncthreads();

    float acc[4][4][4];
#pragma unroll
    for (int i = 0; i < 4; i++)
#pragma unroll
        for (int j = 0; j < 4; j++)
#pragma unroll
            for (int r = 0; r < 4; r++) acc[i][j][r] = 0.f;

#pragma unroll
    for (int kk = 0; kk < 4; kk++) {
        uint32_t bh[4][2], bl[4][2];
#pragma unroll
        for (int ni = 0; ni < 4; ni++) {
            const int n = warpN + ni * 8 + (lane & 7);
            const uint32_t bc = (uint32_t)(kk * 32 + ((lane >> 3) & 1) * 16);
            const uint32_t ad = sbase + P_BHI + SWZ128((uint32_t)(n * 128) + bc);
            LDMATRIX_X2(bh[ni], ad);
            LDMATRIX_X2(bl[ni], ad + 16384);
        }
        uint32_t af[4][4];
#pragma unroll
        for (int mi = 0; mi < 4; mi++) {
            const int m = warpM + mi * 16 + (lane & 15);
            const uint32_t bc = (uint32_t)(kk * 32 + (lane >> 4) * 16);
            const uint32_t ad = sbase + P_AHI + SWZ128((uint32_t)(m * 128) + bc);
            LDMATRIX_X4(af[mi], ad);
        }
#pragma unroll
        for (int mi = 0; mi < 4; mi++)
#pragma unroll
            for (int ni = 0; ni < 4; ni++) MMA16816(acc[mi][ni], af[mi], bh[ni]);
#pragma unroll
        for (int mi = 0; mi < 4; mi++)
#pragma unroll
            for (int ni = 0; ni < 4; ni++) MMA16816(acc[mi][ni], af[mi], bl[ni]);
#pragma unroll
        for (int mi = 0; mi < 4; mi++) {
            const int m = warpM + mi * 16 + (lane & 15);
            const uint32_t bc = (uint32_t)(kk * 32 + (lane >> 4) * 16);
            const uint32_t ad = sbase + P_ALO + SWZ128((uint32_t)(m * 128) + bc);
            LDMATRIX_X4(af[mi], ad);
        }
#pragma unroll
        for (int mi = 0; mi < 4; mi++)
#pragma unroll
            for (int ni = 0; ni < 4; ni++) MMA16816(acc[mi][ni], af[mi], bh[ni]);
    }

    // ---- staged epilogue: 4 passes (cos/sin x hi/lo), coalesced writes ----
    const int orow = tid >> 1, ohalf = tid & 1;
    const int grow = brow + orow;
    const int b = grow >> 16;
    const int rem = grow & 65535;
    const int t = rem >> 4;
    const int h = rem & 15;
    const size_t obase = ((size_t)(((b << 4) + h)) * TT + t) * FD;

#pragma unroll
    for (int pass = 0; pass < 4; pass++) {
        const bool iscos = (pass < 2);
        const bool ishi  = ((pass & 1) == 0);
        __syncthreads();
#pragma unroll
        for (int mi = 0; mi < 4; mi++) {
#pragma unroll
            for (int rr = 0; rr < 2; rr++) {
                const int row = warpM + mi * 16 + (lane >> 2) + rr * 8;
                const float sc = scale_s[row];
#pragma unroll
                for (int ni = 0; ni < 4; ni++) {
                    const int col = warpN + ni * 8 + (lane & 3) * 2;
                    float v0 = acc[mi][ni][rr * 2 + 0];
                    float v1 = acc[mi][ni][rr * 2 + 1];
                    v0 = (iscos ? __cosf(v0) : __sinf(v0)) * sc;
                    v1 = (iscos ? __cosf(v1) : __sinf(v1)) * sc;
                    if (!ishi) {
                        v0 = v0 - __bfloat162float(__float2bfloat16(v0));
                        v1 = v1 - __bfloat162float(__float2bfloat16(v1));
                    }
                    __nv_bfloat162 pk{__float2bfloat16(v0), __float2bfloat16(v1)};
                    *(__nv_bfloat162*)(smem + (size_t)(row * 136 + col) * 2) = pk;
                }
            }
        }
        __syncthreads();
        const int colbase = (iscos ? bcol : bcol + 256);
        char* dp = (char*)((ishi ? outH : outL) + obase + colbase + ohalf * 64);
        const char* sp = smem + orow * 272 + ohalf * 128;
#pragma unroll
        for (int j = 0; j < 16; j++)
            *(uint2*)(dp + j * 8) = *(const uint2*)(sp + j * 8);
    }
}

// =================== kv HMMA: C[f,d] = sum_t Kf[t,f] V[t,d] (+ ksum) =============
#define KV_KHI 0
#define KV_KLO 8192
#define KV_VHI 16384
#define KV_VLO 20480
#define KV_STAGE 24576
#define KV_TOTAL (2 * KV_STAGE)

__global__ __launch_bounds__(256)
void kv_tc(const __nv_bfloat16* __restrict__ Kfh, const __nv_bfloat16* __restrict__ Kfl,
           const __nv_bfloat16* __restrict__ Vhi, const __nv_bfloat16* __restrict__ Vlo,
           float* __restrict__ part) {
    extern __shared__ char smem[];
    const uint32_t sbase = smem_u32(smem);
    const int tid = threadIdx.x, wid = tid >> 5, lane = tid & 31;
    const int bh = blockIdx.y, b = bh >> 4, h = bh & 15;
    const int ftile = blockIdx.x >> 2, tsplit = blockIdx.x & 3;
    const int warpM = wid * 16;
    const int fbase = ftile * 128;
    const size_t tb0 = (size_t)bh * TT + tsplit * 1024;
    const size_t vb0 = (size_t)b * TT + tsplit * 1024;

    float acc[8][4];
#pragma unroll
    for (int i = 0; i < 8; i++)
#pragma unroll
        for (int r = 0; r < 4; r++) acc[i][r] = 0.f;
    float ks = 0.f;

    const int tA0 = tid >> 4, cA0 = tid & 15;
    const int tA1 = (tid + 256) >> 4;
    const uint32_t sA0 = (uint32_t)(tA0 * 256 + ((cA0 ^ (tA0 & 7)) * 16));
    const uint32_t sA1 = (uint32_t)(tA1 * 256 + ((cA0 ^ (tA1 & 7)) * 16));
    const int tV = tid >> 3, cV = tid & 7;
    const uint32_t sV = (uint32_t)(tV * 128 + ((cV ^ (tV & 7)) * 16));

#define KV_ISSUE(ch, stg) do { \
    const uint32_t _st = sbase + (stg) * KV_STAGE; \
    const size_t _t0 = tb0 + (ch) * 32; \
    const size_t _v0 = vb0 + (ch) * 32; \
    CP_ASYNC16(_st + KV_KHI + sA0, Kfh + (_t0 + tA0) * FD + fbase + cA0 * 8); \
    CP_ASYNC16(_st + KV_KHI + sA1, Kfh + (_t0 + tA1) * FD + fbase + cA0 * 8); \
    CP_ASYNC16(_st + KV_KLO + sA0, Kfl + (_t0 + tA0) * FD + fbase + cA0 * 8); \
    CP_ASYNC16(_st + KV_KLO + sA1, Kfl + (_t0 + tA1) * FD + fbase + cA0 * 8); \
    CP_ASYNC16(_st + KV_VHI + sV, Vhi + (_v0 + tV) * DD + h * 64 + cV * 8); \
    CP_ASYNC16(_st + KV_VLO + sV, Vlo + (_v0 + tV) * DD + h * 64 + cV * 8); \
    CP_ASYNC_COMMIT(); \
} while (0)

    KV_ISSUE(0, 0);
    for (int ch = 0; ch < 32; ch++) {
        const int s = ch & 1;
        if (ch + 1 < 32) { KV_ISSUE(ch + 1, s ^ 1); CP_ASYNC_WAIT1(); }
        else             { CP_ASYNC_WAIT0(); }
        __syncthreads();
        const uint32_t st = sbase + s * KV_STAGE;
        {
            const int f = tid >> 1, th = tid & 1;
            const int cf = f >> 3, fo = (f & 7) * 2;
            const char* base = smem + s * KV_STAGE;
#pragma unroll
            for (int j = 0; j < 16; j++) {
                const int t = th * 16 + j;
                const uint32_t off = (uint32_t)(t * 256 + ((cf ^ (t & 7)) * 16) + fo);
                ks += __bfloat162float(*(const __nv_bfloat16*)(base + KV_KHI + off))
                    + __bfloat162float(*(const __nv_bfloat16*)(base + KV_KLO + off));
            }
        }
#pragma unroll
        for (int kt = 0; kt < 2; kt++) {
            const int k0 = kt * 16;
            const int ttA = k0 + (lane & 7) + ((lane >> 4) & 1) * 8;
            const int ccA = (warpM >> 3) + ((lane >> 3) & 1);
            const uint32_t aoff = (uint32_t)(ttA * 256 + ((ccA ^ (ttA & 7)) * 16));
            uint32_t ah[4], al[4];
            LDMATRIX_X4_TRANS(ah, st + KV_KHI + aoff);
            LDMATRIX_X4_TRANS(al, st + KV_KLO + aoff);
            const int ttB = k0 + (lane & 7) + ((lane >> 3) & 1) * 8;
            uint32_t bhf[8][2], blf[8][2];
#pragma unroll
            for (int ni = 0; ni < 8; ni++) {
                const uint32_t boff = (uint32_t)(ttB * 128 + ((ni ^ (ttB & 7)) * 16));
                LDMATRIX_X2_TRANS(bhf[ni], st + KV_VHI + boff);
                LDMATRIX_X2_TRANS(blf[ni], st + KV_VLO + boff);
            }
#pragma unroll
            for (int ni = 0; ni < 8; ni++) MMA16816(acc[ni], ah, bhf[ni]);
#pragma unroll
            for (int ni = 0; ni < 8; ni++) MMA16816(acc[ni], ah, blf[ni]);
#pragma unroll
            for (int ni = 0; ni < 8; ni++) MMA16816(acc[ni], al, bhf[ni]);
        }
        __syncthreads();
    }
#undef KV_ISSUE

    const int pidx = (bh * 4 + ftile) * 4 + tsplit;
    float* pb = part + (size_t)pidx * 8192;
    const int r = warpM + (lane >> 2);
    const int cb = (lane & 3) * 2;
#pragma unroll
    for (int ni = 0; ni < 8; ni++) {
        *(float2*)(pb + r * 64 + ni * 8 + cb)       = make_float2(acc[ni][0], acc[ni][1]);
        *(float2*)(pb + (r + 8) * 64 + ni * 8 + cb) = make_float2(acc[ni][2], acc[ni][3]);
    }
    const float ko = __shfl_xor_sync(0xffffffffu, ks, 1);
    if ((tid & 1) == 0)
        part[KS_OFF + pidx * 128 + (tid >> 1)] = ks + ko;
}

// ---------------- reduce partials -> bf16 split transposed KVT -------------------
__global__ __launch_bounds__(256) void kv_reduce2(const float* __restrict__ part,
                                                  __nv_bfloat16* __restrict__ KVThi,
                                                  __nv_bfloat16* __restrict__ KVTlo) {
    const int bh = blockIdx.x;
    const int tid = threadIdx.x;
    const size_t kb = (size_t)bh * 72 * FD;
    for (int idx = tid; idx < 64 * 512; idx += 256) {
        const int d = idx >> 9, f = idx & 511;
        const int ft = f >> 7, fl = f & 127;
        float v = 0.f;
#pragma unroll
        for (int ts = 0; ts < 4; ts++)
            v += part[(size_t)(((bh * 4 + ft) * 4 + ts)) * 8192 + fl * 64 + d];
        __nv_bfloat16 hi = __float2bfloat16(v);
        KVThi[kb + (size_t)d * FD + f] = hi;
        KVTlo[kb + (size_t)d * FD + f] = __float2bfloat16(v - __bfloat162float(hi));
    }
    for (int f = tid; f < 512; f += 256) {
        const int ft = f >> 7, fl = f & 127;
        float v = 0.f;
#pragma unroll
        for (int ts = 0; ts < 4; ts++)
            v += part[KS_OFF + ((bh * 4 + ft) * 4 + ts) * 128 + fl];
        __nv_bfloat16 hi = __float2bfloat16(v);
        KVThi[kb + (size_t)64 * FD + f] = hi;
        KVTlo[kb + (size_t)64 * FD + f] = __float2bfloat16(v - __bfloat162float(hi));
    }
    const __nv_bfloat16 z = __float2bfloat16(0.f);
    for (int idx = tid; idx < 7 * 512; idx += 256) {
        const int d = 65 + (idx >> 9), f = idx & 511;
        KVThi[kb + (size_t)d * FD + f] = z;
        KVTlo[kb + (size_t)d * FD + f] = z;
    }
}

// =================== qkv HMMA: out = (Qf x KVT^T)[:,0:64] / Z + amax -------------
#define QK_QHI 0
#define QK_QLO 8192
#define QK_BHI 16384
#define QK_BLO 20992
#define QK_STAGE 25600
#define QK_ZS (2 * QK_STAGE)
#define QK_TOTAL (QK_ZS + 512)

__global__ __launch_bounds__(256)
void qkv_tc(const __nv_bfloat16* __restrict__ Qfh, const __nv_bfloat16* __restrict__ Qfl,
            const __nv_bfloat16* __restrict__ KVThi, const __nv_bfloat16* __restrict__ KVTlo,
            float* __restrict__ attn, float* __restrict__ amax) {
    extern __shared__ char smem[];
    const uint32_t sbase = smem_u32(smem);
    const int tid = threadIdx.x, wid = tid >> 5, lane = tid & 31;
    const int bh = blockIdx.y, b = bh >> 4, h = bh & 15;
    const int tb = blockIdx.x;
    const int warpM = (wid >> 1) * 32;
    const int nodd = wid & 1;
    const int ntiles = 5 - nodd;
    const size_t qrow0 = (size_t)bh * TT + tb * 128;
    const size_t kvb = (size_t)bh * 72 * FD;

    float acc[2][5][4];
#pragma unroll
    for (int i = 0; i < 2; i++)
#pragma unroll
        for (int j = 0; j < 5; j++)
#pragma unroll
            for (int r = 0; r < 4; r++) acc[i][j][r] = 0.f;

    const int tQ0 = tid >> 2, cQ = tid & 3;
    const int tQ1 = (tid + 256) >> 2;
    const uint32_t sQ0 = (uint32_t)(tQ0 * 64 + ((cQ ^ ((tQ0 >> 1) & 3)) * 16));
    const uint32_t sQ1 = (uint32_t)(tQ1 * 64 + ((cQ ^ ((tQ1 >> 1) & 3)) * 16));
    const int dB0 = tid >> 2;
    const int dB1 = (tid + 256) >> 2;
    const uint32_t sB0 = (uint32_t)(dB0 * 64 + ((cQ ^ ((dB0 >> 1) & 3)) * 16));
    const uint32_t sB1 = (uint32_t)(dB1 * 64 + ((cQ ^ ((dB1 >> 1) & 3)) * 16));

#define QK_ISSUE(fc, stg) do { \
    const uint32_t _st = sbase + (stg) * QK_STAGE; \
    const int _f0 = (fc) * 32; \
    CP_ASYNC16(_st + QK_QHI + sQ0, Qfh + (qrow0 + tQ0) * FD + _f0 + cQ * 8); \
    CP_ASYNC16(_st + QK_QHI + sQ1, Qfh + (qrow0 + tQ1) * FD + _f0 + cQ * 8); \
    CP_ASYNC16(_st + QK_QLO + sQ0, Qfl + (qrow0 + tQ0) * FD + _f0 + cQ * 8); \
    CP_ASYNC16(_st + QK_QLO + sQ1, Qfl + (qrow0 + tQ1) * FD + _f0 + cQ * 8); \
    CP_ASYNC16(_st + QK_BHI + sB0, KVThi + kvb + (size_t)dB0 * FD + _f0 + cQ * 8); \
    CP_ASYNC16(_st + QK_BLO + sB0, KVTlo + kvb + (size_t)dB0 * FD + _f0 + cQ * 8); \
    if (tid < 32) { \
        CP_ASYNC16(_st + QK_BHI + sB1, KVThi + kvb + (size_t)dB1 * FD + _f0 + cQ * 8); \
        CP_ASYNC16(_st + QK_BLO + sB1, KVTlo + kvb + (size_t)dB1 * FD + _f0 + cQ * 8); \
    } \
    CP_ASYNC_COMMIT(); \
} while (0)

    QK_ISSUE(0, 0);
    for (int fc = 0; fc < 16; fc++) {
        const int s = fc & 1;
        if (fc + 1 < 16) { QK_ISSUE(fc + 1, s ^ 1); CP_ASYNC_WAIT1(); }
        else             { CP_ASYNC_WAIT0(); }
        __syncthreads();
        const uint32_t st = sbase + s * QK_STAGE;
#pragma unroll
        for (int kc = 0; kc < 2; kc++) {
            uint32_t ahf[2][4], alf[2][4];
#pragma unroll
            for (int mi = 0; mi < 2; mi++) {
                const int tt = warpM + mi * 16 + (lane & 7) + ((lane >> 3) & 1) * 8;
                const int cc = kc * 2 + ((lane >> 4) & 1);
                const uint32_t aoff = (uint32_t)(tt * 64 + ((cc ^ ((tt >> 1) & 3)) * 16));
                LDMATRIX_X4(ahf[mi], st + QK_QHI + aoff);
                LDMATRIX_X4(alf[mi], st + QK_QLO + aoff);
            }
            uint32_t bhf[5][2], blf[5][2];
#pragma unroll
            for (int ni = 0; ni < 5; ni++) {
                if (ni < ntiles) {
                    const int gt = ni + nodd * 5;
                    const int dd = gt * 8 + (lane & 7);
                    const int cc = kc * 2 + ((lane >> 3) & 1);
                    const uint32_t boff = (uint32_t)(dd * 64 + ((cc ^ ((dd >> 1) & 3)) * 16));
                    LDMATRIX_X2(bhf[ni], st + QK_BHI + boff);
                    LDMATRIX_X2(blf[ni], st + QK_BLO + boff);
                }
            }
#pragma unroll
            for (int mi = 0; mi < 2; mi++)
#pragma unroll
                for (int ni = 0; ni < 5; ni++)
                    if (ni < ntiles) MMA16816(acc[mi][ni], ahf[mi], bhf[ni]);
#pragma unroll
            for (int mi = 0; mi < 2; mi++)
#pragma unroll
                for (int ni = 0; ni < 5; ni++)
                    if (ni < ntiles) MMA16816(acc[mi][ni], ahf[mi], blf[ni]);
#pragma unroll
            for (int mi = 0; mi < 2; mi++)
#pragma unroll
                for (int ni = 0; ni < 5; ni++)
                    if (ni < ntiles) MMA16816(acc[mi][ni], alf[mi], bhf[ni]);
        }
        __syncthreads();
    }
#undef QK_ISSUE

    float* zsp = (float*)(smem + QK_ZS);
    if (nodd && (lane & 3) == 0) {
#pragma unroll
        for (int mi = 0; mi < 2; mi++) {
            const int r = warpM + mi * 16 + (lane >> 2);
            zsp[r] = acc[mi][3][0];
            zsp[r + 8] = acc[mi][3][2];
        }
    }
    __syncthreads();

    float lmax = 0.f;
    const size_t obase = ((size_t)b * TT + tb * 128) * DD + h * 64;
#pragma unroll
    for (int mi = 0; mi < 2; mi++) {
        const int r = warpM + mi * 16 + (lane >> 2);
        const float iz0 = 1.f / fmaxf(zsp[r], 1e-6f);
        const float iz1 = 1.f / fmaxf(zsp[r + 8], 1e-6f);
#pragma unroll
        for (int ni = 0; ni < 5; ni++) {
            if (ni < ntiles) {
                const int gt = ni + nodd * 5;
                if (gt == 8) continue;
                const int d = gt * 8 + (lane & 3) * 2;
                float o0 = acc[mi][ni][0] * iz0, o1 = acc[mi][ni][1] * iz0;
                float o2 = acc[mi][ni][2] * iz1, o3 = acc[mi][ni][3] * iz1;
                lmax = fmaxf(lmax, fmaxf(fmaxf(fabsf(o0), fabsf(o1)),
                                         fmaxf(fabsf(o2), fabsf(o3))));
                *(float2*)(attn + obase + (size_t)r * DD + d)       = make_float2(o0, o1);
                *(float2*)(attn + obase + (size_t)(r + 8) * DD + d) = make_float2(o2, o3);
            }
        }
    }
    atomicMax((int*)amax, __float_as_int(lmax));
}

// ---------------- launch ----------------------------------------------------------
extern "C" void kernel_launch(void* const* d_in, const int* in_sizes, int n_in,
                              void* d_out, int out_size) {
    (void)in_sizes; (void)n_in; (void)out_size;
    const float* x  = (const float*)d_in[0];
    const float* wq = (const float*)d_in[1];
    const float* wk = (const float*)d_in[2];
    const float* wv = (const float*)d_in[3];
    const float* wo = (const float*)d_in[4];
    const float* rf = (const float*)d_in[5];
    float* out = (float*)d_out;

    float *Qbuf, *Kbuf, *attn, *part, *sclQ, *amax;
    __half *At16, *Wh;
    __nv_bfloat16 *Ahi, *Alo, *Whi, *Wlo, *Qfh, *Qfl, *Kfh, *Kfl, *Vhi, *Vlo, *KVThi, *KVTlo;
    cudaGetSymbolAddress((void**)&Qbuf,  g_Q);
    cudaGetSymbolAddress((void**)&Kbuf,  g_K);
    cudaGetSymbolAddress((void**)&attn,  g_attn);
    cudaGetSymbolAddress((void**)&part,  g_part);
    cudaGetSymbolAddress((void**)&sclQ,  g_scale);
    cudaGetSymbolAddress((void**)&amax,  g_amax);
    cudaGetSymbolAddress((void**)&At16,  g_At16);
    cudaGetSymbolAddress((void**)&Wh,    g_Wh);
    cudaGetSymbolAddress((void**)&Ahi,   g_Ahi);
    cudaGetSymbolAddress((void**)&Alo,   g_Alo);
    cudaGetSymbolAddress((void**)&Whi,   g_Whi);
    cudaGetSymbolAddress((void**)&Wlo,   g_Wlo);
    cudaGetSymbolAddress((void**)&Qfh,   g_Qfh);
    cudaGetSymbolAddress((void**)&Qfl,   g_Qfl);
    cudaGetSymbolAddress((void**)&Kfh,   g_Kfh);
    cudaGetSymbolAddress((void**)&Kfl,   g_Kfl);
    cudaGetSymbolAddress((void**)&Vhi,   g_Vhi);
    cudaGetSymbolAddress((void**)&Vlo,   g_Vlo);
    cudaGetSymbolAddress((void**)&KVThi, g_KVThi);
    cudaGetSymbolAddress((void**)&KVTlo, g_KVTlo);

    // bf16 split buffers aliased onto the old fp32 Q/K scratch
    __nv_bfloat16* Qhi = (__nv_bfloat16*)Qbuf;
    __nv_bfloat16* Qlo = Qhi + (size_t)ROWS * DD;
    __nv_bfloat16* Khi = (__nv_bfloat16*)Kbuf;
    __nv_bfloat16* Klo = Khi + (size_t)ROWS * DD;
    float* sclK = attn;   // free until qkv_tc writes attn

    cudaFuncSetAttribute(gemm_split<1>, cudaFuncAttributeMaxDynamicSharedMemorySize, G_TOTAL);
    cudaFuncSetAttribute(gemm_split<0>, cudaFuncAttributeMaxDynamicSharedMemorySize, G_TOTAL);
    cudaFuncSetAttribute(gemm_f16, cudaFuncAttributeMaxDynamicSharedMemorySize, F_TOTAL);
    cudaFuncSetAttribute(phi_gemm, cudaFuncAttributeMaxDynamicSharedMemorySize, P_TOTAL);
    cudaFuncSetAttribute(kv_tc,    cudaFuncAttributeMaxDynamicSharedMemorySize, KV_TOTAL);
    cudaFuncSetAttribute(qkv_tc,   cudaFuncAttributeMaxDynamicSharedMemorySize, QK_TOTAL);

    const int nX4 = ROWS * DD / 4;
    const int nW4 = DD * DD / 4;
    dim3 gg(DD / 128, ROWS / 128);

    // x split once, reused by the 3 bf16x3 projections
    split_kernel<<<nX4 / 256, 256>>>(x, Ahi, Alo, nX4);

    // projections with fused split(+norm) epilogues
    split_kernel<<<nW4 / 256, 256>>>(wq, Whi, Wlo, nW4);
    gemm_split<1><<<gg, 256, G_TOTAL>>>(Ahi, Alo, Whi, Wlo, Qhi, Qlo, sclQ, ROWS, DD, DD);
    split_kernel<<<nW4 / 256, 256>>>(wk, Whi, Wlo, nW4);
    gemm_split<1><<<gg, 256, G_TOTAL>>>(Ahi, Alo, Whi, Wlo, Khi, Klo, sclK, ROWS, DD, DD);
    split_kernel<<<nW4 / 256, 256>>>(wv, Whi, Wlo, nW4);
    gemm_split<0><<<gg, 256, G_TOTAL>>>(Ahi, Alo, Whi, Wlo, Vhi, Vlo, nullptr, ROWS, DD, DD);

    // rf split (bf16 buffers) then both phis
    split_kernel<<<16, 256>>>(rf, Whi, Wlo, 256 * 64 / 4);
    dim3 gp(2, MR2 / 128);
    phi_gemm<<<gp, 256, P_TOTAL>>>(Qhi, Qlo, Whi, Wlo, sclQ, Qfh, Qfl);
    phi_gemm<<<gp, 256, P_TOTAL>>>(Khi, Klo, Whi, Wlo, sclK, Kfh, Kfl);

    // kv + reduce + qkv (bf16x3 HMMA; qkv tracks attn absmax)
    zero_amax<<<1, 1>>>(amax);
    kv_tc<<<dim3(16, BHN), 256, KV_TOTAL>>>(Kfh, Kfl, Vhi, Vlo, part);
    kv_reduce2<<<BHN, 256>>>(part, KVThi, KVTlo);
    qkv_tc<<<dim3(TT / 128, BHN), 256, QK_TOTAL>>>(Qfh, Qfl, KVThi, KVTlo, attn, amax);

    // output projection: dynamically-scaled fp16 single-pass
    conv16<<<nW4 / 256, 256>>>(wo, Wh, nW4);
    attn_to_f16<<<nX4 / 256, 256>>>(attn, At16, amax, nX4);
    gemm_f16<<<gg, 256, F_TOTAL>>>(At16, Wh, out, amax, ROWS, DD, DD);
}